// round 4
// baseline (speedup 1.0000x reference)
#include <cuda_runtime.h>
#include <cuda_bf16.h>
#include <cstdint>

// ---------------- problem constants ----------------
#define N_MAX   100000
#define E_MAX   3200000
#define FIN     128
#define HID     64
#define OUTD    32

// ---------------- device scratch (direct symbol references only) ----------------
__device__ __align__(16) float g_h  [(size_t)N_MAX * HID];   // 25.6 MB
__device__ __align__(16) float g_agg[(size_t)N_MAX * HID];   // 25.6 MB
__device__ int   g_cnt   [N_MAX];
__device__ float g_dinv  [N_MAX];
__device__ int   g_rowptr[N_MAX + 1];
__device__ int   g_cursor[N_MAX];
__device__ __align__(8) int2 g_csr[E_MAX];                   // (src, norm-as-int)
__device__ int   g_is64;                                     // 1 if indices are int64

// ---------------- index dtype detection ----------------
// int64 indices < 2^31 have zero high words; int32 edge data makes odd words
// nonzero with probability ~1 over 512 samples.
__global__ void k_detect(const int* __restrict__ raw) {
    __shared__ int s_nz;
    if (threadIdx.x == 0) s_nz = 0;
    __syncthreads();
    int nz = 0;
    for (int i = threadIdx.x; i < 512; i += blockDim.x)
        nz |= raw[2 * i + 1];
    if (nz) atomicOr(&s_nz, 1);
    __syncthreads();
    if (threadIdx.x == 0) g_is64 = (s_nz == 0) ? 1 : 0;
}

// load index e from a buffer that is either int32[] or int64[] (flag-selected), clamped
__device__ __forceinline__ int load_idx(const void* buf, size_t e, int is64, int n) {
    int v;
    if (is64) v = (int)((const long long*)buf)[e];
    else      v = ((const int*)buf)[e];
    if ((unsigned)v >= (unsigned)n) v = 0;   // safety clamp: never trap
    return v;
}

// ---------------- CSR build ----------------
__global__ void k_zero_cnt(int n) {
    int i = blockIdx.x * blockDim.x + threadIdx.x;
    if (i < n) g_cnt[i] = 0;
}

__global__ void k_count(const void* __restrict__ ei, int nE, int n) {
    int e = blockIdx.x * blockDim.x + threadIdx.x;
    if (e >= nE) return;
    int is64 = g_is64;
    int c = load_idx(ei, (size_t)nE + e, is64, n);
    atomicAdd(&g_cnt[c], 1);
}

__global__ void k_dinv(int n) {
    int i = blockIdx.x * blockDim.x + threadIdx.x;
    if (i < n) g_dinv[i] = rsqrtf((float)g_cnt[i] + 1.0f);   // +1 self-loop
}

// single-block exclusive scan (Hillis-Steele over 1024-chunks with carry)
__global__ void k_scan(int n) {
    __shared__ int sh[1024];
    __shared__ int s_carry;
    int tid = threadIdx.x;
    if (tid == 0) s_carry = 0;
    __syncthreads();
    for (int base = 0; base < n; base += 1024) {
        int i = base + tid;
        int v = (i < n) ? g_cnt[i] : 0;
        sh[tid] = v;
        __syncthreads();
        #pragma unroll
        for (int off = 1; off < 1024; off <<= 1) {
            int t = (tid >= off) ? sh[tid - off] : 0;
            __syncthreads();
            sh[tid] += t;
            __syncthreads();
        }
        int incl = sh[tid];
        int carry = s_carry;
        int excl = carry + incl - v;
        if (i < n) { g_rowptr[i] = excl; g_cursor[i] = excl; }
        __syncthreads();
        if (tid == 1023) s_carry = carry + sh[1023];
        __syncthreads();
    }
    if (tid == 0) g_rowptr[n] = s_carry;
}

__global__ void k_fill(const void* __restrict__ ei, int nE, int n) {
    int e = blockIdx.x * blockDim.x + threadIdx.x;
    if (e >= nE) return;
    int is64 = g_is64;
    int r = load_idx(ei, (size_t)e, is64, n);
    int c = load_idx(ei, (size_t)nE + e, is64, n);
    float nm = g_dinv[r] * g_dinv[c];
    int pos = atomicAdd(&g_cursor[c], 1);
    if (pos >= 0 && pos < E_MAX)
        g_csr[pos] = make_int2(r, __float_as_int(nm));
}

// ---------------- tiled GEMM: g_h[n, M] = f(X)[n, K] @ W[K, M] ----------------
template<int K, int M, bool RELU, bool X_IS_AGG>
__global__ void k_gemm(const float* __restrict__ Xext,
                       const float* __restrict__ Bk,
                       const float* __restrict__ W, int n) {
    constexpr int NT  = 32;
    constexpr int JPT = M / 8;
    __shared__ __align__(16) float sW[K * M];
    __shared__ float sx[NT][65];

    int tid = threadIdx.x;
    for (int i = tid; i < K * M; i += 256) sW[i] = W[i];

    int n0 = blockIdx.x * NT;
    int nl = tid >> 3;
    int j0 = (tid & 7) * JPT;
    float acc[JPT];
    #pragma unroll
    for (int j = 0; j < JPT; j++) acc[j] = 0.0f;

    for (int kc = 0; kc < K; kc += 64) {
        for (int i = tid; i < NT * 64; i += 256) {
            int nll = i >> 6, k = i & 63;
            int node = n0 + nll;
            float v = 0.0f;
            int kk = kc + k;
            if (node < n) {
                v = X_IS_AGG ? g_agg[(size_t)node * K + kk]
                             : Xext[(size_t)node * K + kk];
                if (RELU) v = fmaxf(v + Bk[kk], 0.0f);
            }
            sx[nll][k] = v;
        }
        __syncthreads();
        #pragma unroll 4
        for (int k = 0; k < 64; k++) {
            float xv = sx[nl][k];
            #pragma unroll
            for (int j = 0; j < JPT; j++)
                acc[j] += xv * sW[(kc + k) * M + j0 + j];
        }
        __syncthreads();
    }

    int node = n0 + nl;
    if (node < n) {
        #pragma unroll
        for (int j = 0; j < JPT; j++)
            g_h[(size_t)node * M + j0 + j] = acc[j];
    }
}

// ---------------- aggregation: gather over CSR ----------------
// g_agg[c] = g_h[c]*dinv[c]^2 + sum_{e in CSR[c]} g_h[src(e)] * norm(e)
template<int H>
__global__ void k_aggregate(int n) {
    constexpr int LPN = H / 4;       // lanes per node
    constexpr int NPW = 32 / LPN;    // nodes per warp
    int gw   = (blockIdx.x * blockDim.x + threadIdx.x) >> 5;
    int lane = threadIdx.x & 31;
    int node = gw * NPW + lane / LPN;
    int fl   = lane % LPN;
    if (node >= n) return;

    float d = g_dinv[node];
    float s = d * d;
    float4 acc = *(const float4*)(g_h + (size_t)node * H + fl * 4);
    acc.x *= s; acc.y *= s; acc.z *= s; acc.w *= s;

    int beg = g_rowptr[node];
    int end = g_rowptr[node + 1];
    int e = beg;
    for (; e + 1 < end; e += 2) {
        int2 p0 = g_csr[e];
        int2 p1 = g_csr[e + 1];
        float4 v0 = *(const float4*)(g_h + (size_t)p0.x * H + fl * 4);
        float4 v1 = *(const float4*)(g_h + (size_t)p1.x * H + fl * 4);
        float n0 = __int_as_float(p0.y);
        float n1 = __int_as_float(p1.y);
        acc.x += v0.x * n0; acc.y += v0.y * n0; acc.z += v0.z * n0; acc.w += v0.w * n0;
        acc.x += v1.x * n1; acc.y += v1.y * n1; acc.z += v1.z * n1; acc.w += v1.w * n1;
    }
    if (e < end) {
        int2 p = g_csr[e];
        float nm = __int_as_float(p.y);
        float4 v = *(const float4*)(g_h + (size_t)p.x * H + fl * 4);
        acc.x += v.x * nm; acc.y += v.y * nm; acc.z += v.z * nm; acc.w += v.w * nm;
    }
    *(float4*)(g_agg + (size_t)node * H + fl * 4) = acc;
}

// final z = g_agg + b3, written into d_out[EL ...]
__global__ void k_final_z(const float* __restrict__ b3, float* __restrict__ zout, int n) {
    int idx = blockIdx.x * blockDim.x + threadIdx.x;
    if (idx >= n * OUTD) return;
    zout[idx] = g_agg[idx] + b3[idx & (OUTD - 1)];
}

// ---------------- link-prediction decoder ----------------
// 64 edges / block, 256 threads, 4 threads per edge (16 hidden units each)
__global__ void k_decode(const float* __restrict__ z, const void* __restrict__ eli,
                         const float* __restrict__ W1, const float* __restrict__ b1,
                         const float* __restrict__ W2, const float* __restrict__ b2,
                         float* __restrict__ out, int nE, int nNodes) {
    __shared__ __align__(16) float sW1[64 * 64];
    __shared__ __align__(16) float sef[64 * 68];
    __shared__ float sw2[64];
    __shared__ float sb1[64];

    int tid = threadIdx.x;
    for (int i = tid; i < 64 * 64; i += 256) sW1[i] = W1[i];
    if (tid < 64) { sw2[tid] = W2[tid]; sb1[tid] = b1[tid]; }

    int is64 = g_is64;
    int e0 = blockIdx.x * 64;
    for (int i = tid; i < 64 * 16; i += 256) {
        int el = i >> 4, q = i & 15;
        int eg = e0 + el;
        float4 v = make_float4(0.f, 0.f, 0.f, 0.f);
        if (eg < nE) {
            size_t pos = (q < 8) ? (size_t)eg : (size_t)nE + eg;
            int node = load_idx(eli, pos, is64, nNodes);
            v = *(const float4*)(z + (size_t)node * OUTD + (q & 7) * 4);
        }
        *(float4*)(&sef[el * 68 + q * 4]) = v;
    }
    __syncthreads();

    int el = tid >> 2;
    int j0 = (tid & 3) * 16;
    float acc[16];
    #pragma unroll
    for (int j = 0; j < 16; j++) acc[j] = sb1[j0 + j];

    const float* ef = &sef[el * 68];
    #pragma unroll 4
    for (int k = 0; k < 64; k++) {
        float xk = ef[k];
        #pragma unroll
        for (int j = 0; j < 16; j++)
            acc[j] += xk * sW1[k * 64 + j0 + j];
    }
    float p = 0.0f;
    #pragma unroll
    for (int j = 0; j < 16; j++) p += fmaxf(acc[j], 0.0f) * sw2[j0 + j];
    p += __shfl_down_sync(0xffffffffu, p, 2);
    p += __shfl_down_sync(0xffffffffu, p, 1);
    int eg = e0 + el;
    if ((tid & 3) == 0 && eg < nE) out[eg] = p + b2[0];
}

// ---------------- host launcher ----------------
extern "C" void kernel_launch(void* const* d_in, const int* in_sizes, int n_in,
                              void* d_out, int out_size) {
    const float* x    = (const float*)d_in[0];
    const void*  ei   = d_in[1];
    const void*  eli  = d_in[2];
    const float* W1   = (const float*)d_in[3];
    const float* b1   = (const float*)d_in[4];
    const float* W2   = (const float*)d_in[5];
    const float* b2   = (const float*)d_in[6];
    const float* W3   = (const float*)d_in[7];
    const float* b3   = (const float*)d_in[8];
    const float* lpW1 = (const float*)d_in[9];
    const float* lpb1 = (const float*)d_in[10];
    const float* lpW2 = (const float*)d_in[11];
    const float* lpb2 = (const float*)d_in[12];
    float* out = (float*)d_out;

    int N  = in_sizes[0] / FIN;
    int E  = in_sizes[1] / 2;
    int EL = in_sizes[2] / 2;

    const int T = 256;
    int nBlkN = (N + T - 1) / T;
    int nBlkE = (E + T - 1) / T;

    // --- dtype detection + CSR build + normalization ---
    k_detect<<<1, 256>>>((const int*)ei);
    k_zero_cnt<<<nBlkN, T>>>(N);
    k_count<<<nBlkE, T>>>(ei, E, N);
    k_dinv<<<nBlkN, T>>>(N);
    k_scan<<<1, 1024>>>(N);
    k_fill<<<nBlkE, T>>>(ei, E, N);

    int gemmBlocks = (N + 31) / 32;
    auto aggGrid = [&](int nodesPerWarp) {
        int warps = (N + nodesPerWarp - 1) / nodesPerWarp;
        return (warps * 32 + T - 1) / T;
    };

    // --- layer 1: h = x @ W1 ; agg = gather(h) ---
    k_gemm<FIN, HID, false, false><<<gemmBlocks, T>>>(x, nullptr, W1, N);
    k_aggregate<HID><<<aggGrid(2), T>>>(N);

    // --- layer 2: h = relu(agg + b1) @ W2 ; agg = gather(h) ---
    k_gemm<HID, HID, true, true><<<gemmBlocks, T>>>(nullptr, b1, W2, N);
    k_aggregate<HID><<<aggGrid(2), T>>>(N);

    // --- layer 3: h = relu(agg + b2) @ W3 ; agg = gather(h) ---
    k_gemm<HID, OUTD, true, true><<<gemmBlocks, T>>>(nullptr, b2, W3, N);
    k_aggregate<OUTD><<<aggGrid(4), T>>>(N);

    // --- z = agg + b3 -> out[EL ...] ---
    float* zout = out + EL;
    k_final_z<<<(N * OUTD + T - 1) / T, T>>>(b3, zout, N);

    // --- decoder: link_pred -> out[0 .. EL) ---
    int decBlocks = (EL + 63) / 64;
    k_decode<<<decBlocks, T>>>(zout, eli, lpW1, lpb1, lpW2, lpb2, out, EL, N);
}

// round 5
// speedup vs baseline: 2.2250x; 2.2250x over previous
#include <cuda_runtime.h>
#include <cuda_bf16.h>
#include <cstdint>

#define N_MAX   100000
#define E_MAX   3200000
#define FIN     128
#define HID     64
#define OUTD    32

__device__ __align__(16) float g_h  [(size_t)N_MAX * HID];
__device__ __align__(16) float g_agg[(size_t)N_MAX * HID];
__device__ int   g_cnt   [N_MAX];
__device__ float g_dinv  [N_MAX];
__device__ int   g_rowptr[N_MAX + 1];
__device__ int   g_cursor[N_MAX];
__device__ __align__(8) int2 g_csr[E_MAX];
__device__ int   g_is64;

__device__ __forceinline__ unsigned long long fma2(unsigned long long a,
                                                   unsigned long long b,
                                                   unsigned long long c) {
    unsigned long long d;
    asm("fma.rn.f32x2 %0, %1, %2, %3;" : "=l"(d) : "l"(a), "l"(b), "l"(c));
    return d;
}
__device__ __forceinline__ unsigned long long pack2(float lo, float hi) {
    unsigned long long r;
    asm("mov.b64 %0, {%1, %2};" : "=l"(r) : "f"(lo), "f"(hi));
    return r;
}
__device__ __forceinline__ float2 unpack2(unsigned long long v) {
    float2 r;
    asm("mov.b64 {%0, %1}, %2;" : "=f"(r.x), "=f"(r.y) : "l"(v));
    return r;
}

__global__ void k_detect(const int* __restrict__ raw) {
    __shared__ int s_nz;
    if (threadIdx.x == 0) s_nz = 0;
    __syncthreads();
    int nz = 0;
    for (int i = threadIdx.x; i < 512; i += blockDim.x)
        nz |= raw[2 * i + 1];
    if (nz) atomicOr(&s_nz, 1);
    __syncthreads();
    if (threadIdx.x == 0) g_is64 = (s_nz == 0) ? 1 : 0;
}

__device__ __forceinline__ int load_idx(const void* buf, size_t e, int is64, int n) {
    int v;
    if (is64) v = (int)((const long long*)buf)[e];
    else      v = ((const int*)buf)[e];
    if ((unsigned)v >= (unsigned)n) v = 0;
    return v;
}

__global__ void k_zero_cnt(int n) {
    int i = blockIdx.x * blockDim.x + threadIdx.x;
    if (i < n) g_cnt[i] = 0;
}

__global__ void k_count(const void* __restrict__ ei, int nE, int n) {
    int e = blockIdx.x * blockDim.x + threadIdx.x;
    if (e >= nE) return;
    int is64 = g_is64;
    int c = load_idx(ei, (size_t)nE + e, is64, n);
    atomicAdd(&g_cnt[c], 1);
}

__global__ void k_scan(int n) {
    __shared__ int sh[1024];
    __shared__ int s_carry;
    int tid = threadIdx.x;
    if (tid == 0) s_carry = 0;
    __syncthreads();
    for (int base = 0; base < n; base += 1024) {
        int i = base + tid;
        int v = (i < n) ? g_cnt[i] : 0;
        if (i < n) g_dinv[i] = rsqrtf((float)v + 1.0f);
        sh[tid] = v;
        __syncthreads();
        #pragma unroll
        for (int off = 1; off < 1024; off <<= 1) {
            int t = (tid >= off) ? sh[tid - off] : 0;
            __syncthreads();
            sh[tid] += t;
            __syncthreads();
        }
        int incl = sh[tid];
        int carry = s_carry;
        int excl = carry + incl - v;
        if (i < n) { g_rowptr[i] = excl; g_cursor[i] = excl; }
        __syncthreads();
        if (tid == 1023) s_carry = carry + sh[1023];
        __syncthreads();
    }
    if (tid == 0) g_rowptr[n] = s_carry;
}

__global__ void k_fill(const void* __restrict__ ei, int nE, int n) {
    int e = blockIdx.x * blockDim.x + threadIdx.x;
    if (e >= nE) return;
    int is64 = g_is64;
    int r = load_idx(ei, (size_t)e, is64, n);
    int c = load_idx(ei, (size_t)nE + e, is64, n);
    float nm = g_dinv[r] * g_dinv[c];
    int pos = atomicAdd(&g_cursor[c], 1);
    if (pos >= 0 && pos < E_MAX)
        g_csr[pos] = make_int2(r, __float_as_int(nm));
}

template<int K, int M, bool RELU, bool X_IS_AGG>
__global__ void k_gemm(const float* __restrict__ Xext,
                       const float* __restrict__ Bk,
                       const float* __restrict__ W, int n) {
    constexpr int KC = 64;
    constexpr int JG = M / 8;
    constexpr int THREADS = 16 * JG;
    constexpr int XS = 132;
    __shared__ float sW[KC * M];
    __shared__ float sXT[KC][XS];

    int tid = threadIdx.x;
    int jg  = tid & (JG - 1);
    int ng  = tid / JG;
    int n0  = blockIdx.x * 128;

    unsigned long long acc2[8][4];
    #pragma unroll
    for (int e = 0; e < 8; e++)
        #pragma unroll
        for (int jj = 0; jj < 4; jj++) acc2[e][jj] = 0ull;

    const float* src = X_IS_AGG ? (const float*)g_agg : Xext;

    for (int kc = 0; kc < K; kc += KC) {
        for (int i = tid; i < KC * M; i += THREADS)
            sW[i] = W[(size_t)kc * M + i];
        for (int nl = tid; nl < 128; nl += THREADS) {
            int node = n0 + nl;
            #pragma unroll
            for (int q = 0; q < KC / 4; q++) {
                float4 v = make_float4(0.f, 0.f, 0.f, 0.f);
                if (node < n) {
                    v = *(const float4*)(src + (size_t)node * K + kc + q * 4);
                    if (RELU) {
                        v.x = fmaxf(v.x + Bk[kc + q * 4 + 0], 0.f);
                        v.y = fmaxf(v.y + Bk[kc + q * 4 + 1], 0.f);
                        v.z = fmaxf(v.z + Bk[kc + q * 4 + 2], 0.f);
                        v.w = fmaxf(v.w + Bk[kc + q * 4 + 3], 0.f);
                    }
                }
                sXT[q * 4 + 0][nl] = v.x;
                sXT[q * 4 + 1][nl] = v.y;
                sXT[q * 4 + 2][nl] = v.z;
                sXT[q * 4 + 3][nl] = v.w;
            }
        }
        __syncthreads();

        #pragma unroll 4
        for (int k = 0; k < KC; k++) {
            float4 a0 = *(const float4*)&sXT[k][ng * 8];
            float4 a1 = *(const float4*)&sXT[k][ng * 8 + 4];
            const float2* wr = (const float2*)&sW[k * M + jg * 8];
            unsigned long long w0 = pack2(wr[0].x, wr[0].y);
            unsigned long long w1 = pack2(wr[1].x, wr[1].y);
            unsigned long long w2 = pack2(wr[2].x, wr[2].y);
            unsigned long long w3 = pack2(wr[3].x, wr[3].y);
            float av[8] = {a0.x, a0.y, a0.z, a0.w, a1.x, a1.y, a1.z, a1.w};
            #pragma unroll
            for (int e = 0; e < 8; e++) {
                unsigned long long x2 = pack2(av[e], av[e]);
                acc2[e][0] = fma2(x2, w0, acc2[e][0]);
                acc2[e][1] = fma2(x2, w1, acc2[e][1]);
                acc2[e][2] = fma2(x2, w2, acc2[e][2]);
                acc2[e][3] = fma2(x2, w3, acc2[e][3]);
            }
        }
        __syncthreads();
    }

    #pragma unroll
    for (int e = 0; e < 8; e++) {
        int node = n0 + ng * 8 + e;
        if (node < n) {
            float* dst = g_h + (size_t)node * M + jg * 8;
            #pragma unroll
            for (int jj = 0; jj < 4; jj++)
                *(float2*)(dst + jj * 2) = unpack2(acc2[e][jj]);
        }
    }
}

// FINAL=true: dst = zout with +bias; else dst = g_agg
template<int H, bool FINAL>
__global__ void k_aggregate(int n, const float* __restrict__ bias,
                            float* __restrict__ zout) {
    constexpr int LPN = H / 4;
    constexpr int NPW = 32 / LPN;
    int gw   = (blockIdx.x * blockDim.x + threadIdx.x) >> 5;
    int lane = threadIdx.x & 31;
    int node = gw * NPW + lane / LPN;
    int fl   = lane % LPN;
    if (node >= n) return;

    float d = g_dinv[node];
    float s = d * d;
    float4 acc = *(const float4*)(g_h + (size_t)node * H + fl * 4);
    acc.x *= s; acc.y *= s; acc.z *= s; acc.w *= s;

    int beg = g_rowptr[node];
    int end = g_rowptr[node + 1];
    int e = beg;
    for (; e + 1 < end; e += 2) {
        int2 p0 = g_csr[e];
        int2 p1 = g_csr[e + 1];
        float4 v0 = *(const float4*)(g_h + (size_t)p0.x * H + fl * 4);
        float4 v1 = *(const float4*)(g_h + (size_t)p1.x * H + fl * 4);
        float n0 = __int_as_float(p0.y);
        float n1 = __int_as_float(p1.y);
        acc.x += v0.x * n0; acc.y += v0.y * n0; acc.z += v0.z * n0; acc.w += v0.w * n0;
        acc.x += v1.x * n1; acc.y += v1.y * n1; acc.z += v1.z * n1; acc.w += v1.w * n1;
    }
    if (e < end) {
        int2 p = g_csr[e];
        float nm = __int_as_float(p.y);
        float4 v = *(const float4*)(g_h + (size_t)p.x * H + fl * 4);
        acc.x += v.x * nm; acc.y += v.y * nm; acc.z += v.z * nm; acc.w += v.w * nm;
    }
    float* dst;
    if (FINAL) {
        float4 bb = *(const float4*)(bias + fl * 4);
        acc.x += bb.x; acc.y += bb.y; acc.z += bb.z; acc.w += bb.w;
        dst = zout;
    } else {
        dst = g_agg;
    }
    *(float4*)(dst + (size_t)node * H + fl * 4) = acc;
}

#define DEC_E 128
#define SEFS  132
__global__ void k_decode(const float* __restrict__ z, const void* __restrict__ eli,
                         const float* __restrict__ W1, const float* __restrict__ b1,
                         const float* __restrict__ W2, const float* __restrict__ b2,
                         float* __restrict__ out, int nE, int nNodes) {
    __shared__ float sW1[64 * 64];
    __shared__ float sefT[64][SEFS];
    __shared__ float sred[8][DEC_E];
    __shared__ float sb1[64], sw2[64];

    int tid = threadIdx.x;
    for (int i = tid; i < 64 * 64; i += 128) sW1[i] = W1[i];
    if (tid < 64) { sb1[tid] = b1[tid]; sw2[tid] = W2[tid]; }

    int is64 = g_is64;
    int e0 = blockIdx.x * DEC_E;

    {
        int eg_ = e0 + tid;
        bool valid = eg_ < nE;
        int sidx = 0, didx = 0;
        if (valid) {
            sidx = load_idx(eli, (size_t)eg_, is64, nNodes);
            didx = load_idx(eli, (size_t)nE + eg_, is64, nNodes);
        }
        #pragma unroll
        for (int q = 0; q < 8; q++) {
            float4 v = valid ? *(const float4*)(z + (size_t)sidx * OUTD + q * 4)
                             : make_float4(0.f, 0.f, 0.f, 0.f);
            sefT[q * 4 + 0][tid] = v.x; sefT[q * 4 + 1][tid] = v.y;
            sefT[q * 4 + 2][tid] = v.z; sefT[q * 4 + 3][tid] = v.w;
        }
        #pragma unroll
        for (int q = 0; q < 8; q++) {
            float4 v = valid ? *(const float4*)(z + (size_t)didx * OUTD + q * 4)
                             : make_float4(0.f, 0.f, 0.f, 0.f);
            sefT[32 + q * 4 + 0][tid] = v.x; sefT[32 + q * 4 + 1][tid] = v.y;
            sefT[32 + q * 4 + 2][tid] = v.z; sefT[32 + q * 4 + 3][tid] = v.w;
        }
    }
    __syncthreads();

    int jg = tid & 7;
    int eg = tid >> 3;

    unsigned long long acc2[8][4];
    {
        const float2* bb = (const float2*)&sb1[jg * 8];
        unsigned long long c0 = pack2(bb[0].x, bb[0].y);
        unsigned long long c1 = pack2(bb[1].x, bb[1].y);
        unsigned long long c2 = pack2(bb[2].x, bb[2].y);
        unsigned long long c3 = pack2(bb[3].x, bb[3].y);
        #pragma unroll
        for (int e = 0; e < 8; e++) {
            acc2[e][0] = c0; acc2[e][1] = c1; acc2[e][2] = c2; acc2[e][3] = c3;
        }
    }

    #pragma unroll 4
    for (int k = 0; k < 64; k++) {
        float4 a0 = *(const float4*)&sefT[k][eg * 8];
        float4 a1 = *(const float4*)&sefT[k][eg * 8 + 4];
        const float2* wr = (const float2*)&sW1[k * 64 + jg * 8];
        unsigned long long w0 = pack2(wr[0].x, wr[0].y);
        unsigned long long w1 = pack2(wr[1].x, wr[1].y);
        unsigned long long w2 = pack2(wr[2].x, wr[2].y);
        unsigned long long w3 = pack2(wr[3].x, wr[3].y);
        float av[8] = {a0.x, a0.y, a0.z, a0.w, a1.x, a1.y, a1.z, a1.w};
        #pragma unroll
        for (int e = 0; e < 8; e++) {
            unsigned long long x2 = pack2(av[e], av[e]);
            acc2[e][0] = fma2(x2, w0, acc2[e][0]);
            acc2[e][1] = fma2(x2, w1, acc2[e][1]);
            acc2[e][2] = fma2(x2, w2, acc2[e][2]);
            acc2[e][3] = fma2(x2, w3, acc2[e][3]);
        }
    }

    {
        float w2v[8];
        #pragma unroll
        for (int j = 0; j < 8; j++) w2v[j] = sw2[jg * 8 + j];
        #pragma unroll
        for (int e = 0; e < 8; e++) {
            float p = 0.f;
            #pragma unroll
            for (int jj = 0; jj < 4; jj++) {
                float2 v = unpack2(acc2[e][jj]);
                p += fmaxf(v.x, 0.f) * w2v[jj * 2] + fmaxf(v.y, 0.f) * w2v[jj * 2 + 1];
            }
            sred[jg][eg * 8 + e] = p;
        }
    }
    __syncthreads();

    {
        float t = 0.f;
        #pragma unroll
        for (int j = 0; j < 8; j++) t += sred[j][tid];
        int eg_ = e0 + tid;
        if (eg_ < nE) out[eg_] = t + b2[0];
    }
}

extern "C" void kernel_launch(void* const* d_in, const int* in_sizes, int n_in,
                              void* d_out, int out_size) {
    const float* x    = (const float*)d_in[0];
    const void*  ei   = d_in[1];
    const void*  eli  = d_in[2];
    const float* W1   = (const float*)d_in[3];
    const float* b1   = (const float*)d_in[4];
    const float* W2   = (const float*)d_in[5];
    const float* b2   = (const float*)d_in[6];
    const float* W3   = (const float*)d_in[7];
    const float* b3   = (const float*)d_in[8];
    const float* lpW1 = (const float*)d_in[9];
    const float* lpb1 = (const float*)d_in[10];
    const float* lpW2 = (const float*)d_in[11];
    const float* lpb2 = (const float*)d_in[12];
    float* out = (float*)d_out;

    int N  = in_sizes[0] / FIN;
    int E  = in_sizes[1] / 2;
    int EL = in_sizes[2] / 2;

    const int T = 256;
    int nBlkN = (N + T - 1) / T;
    int nBlkE = (E + T - 1) / T;

    k_detect<<<1, 256>>>((const int*)ei);
    k_zero_cnt<<<nBlkN, T>>>(N);
    k_count<<<nBlkE, T>>>(ei, E, N);
    k_scan<<<1, 1024>>>(N);
    k_fill<<<nBlkE, T>>>(ei, E, N);

    int gemmBlocks = (N + 127) / 128;
    auto aggGrid = [&](int nodesPerWarp) {
        int warps = (N + nodesPerWarp - 1) / nodesPerWarp;
        return (warps * 32 + T - 1) / T;
    };

    float* zout = out + EL;

    k_gemm<FIN, HID, false, false><<<gemmBlocks, 128>>>(x, nullptr, W1, N);
    k_aggregate<HID, false><<<aggGrid(2), T>>>(N, nullptr, nullptr);

    k_gemm<HID, HID, true, true><<<gemmBlocks, 128>>>(nullptr, b1, W2, N);
    k_aggregate<HID, false><<<aggGrid(2), T>>>(N, nullptr, nullptr);

    k_gemm<HID, OUTD, true, true><<<gemmBlocks, 64>>>(nullptr, b2, W3, N);
    k_aggregate<OUTD, true><<<aggGrid(4), T>>>(N, b3, zout);

    int decBlocks = (EL + DEC_E - 1) / DEC_E;
    k_decode<<<decBlocks, 128>>>(zout, eli, lpW1, lpb1, lpW2, lpb2, out, EL, N);
}

// round 6
// speedup vs baseline: 2.7156x; 1.2205x over previous
#include <cuda_runtime.h>
#include <cuda_bf16.h>
#include <cstdint>

#define N_MAX   100000
#define E_MAX   3200000
#define FIN     128
#define HID     64
#define OUTD    32
#define SCAN_B  ((N_MAX + 1023) / 1024)   // 98

__device__ __align__(16) float g_h  [(size_t)N_MAX * HID];
__device__ __align__(16) float g_agg[(size_t)N_MAX * HID];
__device__ int   g_cnt   [N_MAX];
__device__ float g_dinv  [N_MAX];
__device__ int   g_rowptr[N_MAX + 1];
__device__ int   g_cursor[N_MAX];
__device__ int   g_bsum  [SCAN_B];
__device__ int   g_boff  [SCAN_B];
__device__ __align__(8) int2 g_csr[E_MAX];
__device__ int   g_is64;

__device__ __forceinline__ unsigned long long fma2(unsigned long long a,
                                                   unsigned long long b,
                                                   unsigned long long c) {
    unsigned long long d;
    asm("fma.rn.f32x2 %0, %1, %2, %3;" : "=l"(d) : "l"(a), "l"(b), "l"(c));
    return d;
}
__device__ __forceinline__ unsigned long long pack2(float lo, float hi) {
    unsigned long long r;
    asm("mov.b64 %0, {%1, %2};" : "=l"(r) : "f"(lo), "f"(hi));
    return r;
}
__device__ __forceinline__ float2 unpack2(unsigned long long v) {
    float2 r;
    asm("mov.b64 {%0, %1}, %2;" : "=f"(r.x), "=f"(r.y) : "l"(v));
    return r;
}

__global__ void k_detect(const int* __restrict__ raw) {
    __shared__ int s_nz;
    if (threadIdx.x == 0) s_nz = 0;
    __syncthreads();
    int nz = 0;
    for (int i = threadIdx.x; i < 512; i += blockDim.x)
        nz |= raw[2 * i + 1];
    if (nz) atomicOr(&s_nz, 1);
    __syncthreads();
    if (threadIdx.x == 0) g_is64 = (s_nz == 0) ? 1 : 0;
}

__device__ __forceinline__ int load_idx(const void* buf, size_t e, int is64, int n) {
    int v;
    if (is64) v = (int)((const long long*)buf)[e];
    else      v = ((const int*)buf)[e];
    if ((unsigned)v >= (unsigned)n) v = 0;
    return v;
}

__global__ void k_zero_cnt(int n) {
    int i = blockIdx.x * blockDim.x + threadIdx.x;
    if (i < n) g_cnt[i] = 0;
}

__global__ void k_count(const void* __restrict__ ei, int nE, int n) {
    int e = blockIdx.x * blockDim.x + threadIdx.x;
    if (e >= nE) return;
    int is64 = g_is64;
    int c = load_idx(ei, (size_t)nE + e, is64, n);
    atomicAdd(&g_cnt[c], 1);
}

// ---- phase 1: per-block local scan (grid = SCAN_B, block = 1024) ----
// rowptr[i] <- block-local exclusive prefix; g_bsum[b] <- block total; dinv fused.
__global__ void k_scan1(int n) {
    __shared__ int sh[1024];
    int tid = threadIdx.x;
    int i = blockIdx.x * 1024 + tid;
    int v = (i < n) ? g_cnt[i] : 0;
    if (i < n) g_dinv[i] = rsqrtf((float)v + 1.0f);   // +1 self-loop
    sh[tid] = v;
    __syncthreads();
    #pragma unroll
    for (int off = 1; off < 1024; off <<= 1) {
        int t = (tid >= off) ? sh[tid - off] : 0;
        __syncthreads();
        sh[tid] += t;
        __syncthreads();
    }
    if (i < n) g_rowptr[i] = sh[tid] - v;
    if (tid == 1023) g_bsum[blockIdx.x] = sh[1023];
}

// ---- phase 2: scan the SCAN_B block totals (1 block, 128 threads) ----
__global__ void k_scan2(int n) {
    __shared__ int sh[128];
    int tid = threadIdx.x;
    int v = (tid < SCAN_B) ? g_bsum[tid] : 0;
    sh[tid] = v;
    __syncthreads();
    #pragma unroll
    for (int off = 1; off < 128; off <<= 1) {
        int t = (tid >= off) ? sh[tid - off] : 0;
        __syncthreads();
        sh[tid] += t;
        __syncthreads();
    }
    if (tid < SCAN_B) g_boff[tid] = sh[tid] - v;
    if (tid == 127) g_rowptr[n] = sh[127];
}

// ---- phase 3: add block offsets, init cursor ----
__global__ void k_scan3(int n) {
    int i = blockIdx.x * blockDim.x + threadIdx.x;
    if (i >= n) return;
    int r = g_rowptr[i] + g_boff[i >> 10];
    g_rowptr[i] = r;
    g_cursor[i] = r;
}

__global__ void k_fill(const void* __restrict__ ei, int nE, int n) {
    int e = blockIdx.x * blockDim.x + threadIdx.x;
    if (e >= nE) return;
    int is64 = g_is64;
    int r = load_idx(ei, (size_t)e, is64, n);
    int c = load_idx(ei, (size_t)nE + e, is64, n);
    float nm = g_dinv[r] * g_dinv[c];
    int pos = atomicAdd(&g_cursor[c], 1);
    if (pos >= 0 && pos < E_MAX)
        g_csr[pos] = make_int2(r, __float_as_int(nm));
}

template<int K, int M, bool RELU, bool X_IS_AGG>
__global__ void k_gemm(const float* __restrict__ Xext,
                       const float* __restrict__ Bk,
                       const float* __restrict__ W, int n) {
    constexpr int KC = 64;
    constexpr int JG = M / 8;
    constexpr int THREADS = 16 * JG;
    constexpr int XS = 132;
    __shared__ float sW[KC * M];
    __shared__ float sXT[KC][XS];

    int tid = threadIdx.x;
    int jg  = tid & (JG - 1);
    int ng  = tid / JG;
    int n0  = blockIdx.x * 128;

    unsigned long long acc2[8][4];
    #pragma unroll
    for (int e = 0; e < 8; e++)
        #pragma unroll
        for (int jj = 0; jj < 4; jj++) acc2[e][jj] = 0ull;

    const float* src = X_IS_AGG ? (const float*)g_agg : Xext;

    for (int kc = 0; kc < K; kc += KC) {
        for (int i = tid; i < KC * M; i += THREADS)
            sW[i] = W[(size_t)kc * M + i];
        for (int nl = tid; nl < 128; nl += THREADS) {
            int node = n0 + nl;
            #pragma unroll
            for (int q = 0; q < KC / 4; q++) {
                float4 v = make_float4(0.f, 0.f, 0.f, 0.f);
                if (node < n) {
                    v = *(const float4*)(src + (size_t)node * K + kc + q * 4);
                    if (RELU) {
                        v.x = fmaxf(v.x + Bk[kc + q * 4 + 0], 0.f);
                        v.y = fmaxf(v.y + Bk[kc + q * 4 + 1], 0.f);
                        v.z = fmaxf(v.z + Bk[kc + q * 4 + 2], 0.f);
                        v.w = fmaxf(v.w + Bk[kc + q * 4 + 3], 0.f);
                    }
                }
                sXT[q * 4 + 0][nl] = v.x;
                sXT[q * 4 + 1][nl] = v.y;
                sXT[q * 4 + 2][nl] = v.z;
                sXT[q * 4 + 3][nl] = v.w;
            }
        }
        __syncthreads();

        #pragma unroll 4
        for (int k = 0; k < KC; k++) {
            float4 a0 = *(const float4*)&sXT[k][ng * 8];
            float4 a1 = *(const float4*)&sXT[k][ng * 8 + 4];
            const float2* wr = (const float2*)&sW[k * M + jg * 8];
            unsigned long long w0 = pack2(wr[0].x, wr[0].y);
            unsigned long long w1 = pack2(wr[1].x, wr[1].y);
            unsigned long long w2 = pack2(wr[2].x, wr[2].y);
            unsigned long long w3 = pack2(wr[3].x, wr[3].y);
            float av[8] = {a0.x, a0.y, a0.z, a0.w, a1.x, a1.y, a1.z, a1.w};
            #pragma unroll
            for (int e = 0; e < 8; e++) {
                unsigned long long x2 = pack2(av[e], av[e]);
                acc2[e][0] = fma2(x2, w0, acc2[e][0]);
                acc2[e][1] = fma2(x2, w1, acc2[e][1]);
                acc2[e][2] = fma2(x2, w2, acc2[e][2]);
                acc2[e][3] = fma2(x2, w3, acc2[e][3]);
            }
        }
        __syncthreads();
    }

    #pragma unroll
    for (int e = 0; e < 8; e++) {
        int node = n0 + ng * 8 + e;
        if (node < n) {
            float* dst = g_h + (size_t)node * M + jg * 8;
            #pragma unroll
            for (int jj = 0; jj < 4; jj++)
                *(float2*)(dst + jj * 2) = unpack2(acc2[e][jj]);
        }
    }
}

// FINAL=true: dst = zout with +bias; else dst = g_agg
template<int H, bool FINAL>
__global__ void k_aggregate(int n, const float* __restrict__ bias,
                            float* __restrict__ zout) {
    constexpr int LPN = H / 4;
    constexpr int NPW = 32 / LPN;
    int gw   = (blockIdx.x * blockDim.x + threadIdx.x) >> 5;
    int lane = threadIdx.x & 31;
    int node = gw * NPW + lane / LPN;
    int fl   = lane % LPN;
    if (node >= n) return;

    float d = g_dinv[node];
    float s = d * d;
    float4 acc = *(const float4*)(g_h + (size_t)node * H + fl * 4);
    acc.x *= s; acc.y *= s; acc.z *= s; acc.w *= s;

    int beg = g_rowptr[node];
    int end = g_rowptr[node + 1];
    int e = beg;
    for (; e + 1 < end; e += 2) {
        int2 p0 = g_csr[e];
        int2 p1 = g_csr[e + 1];
        float4 v0 = *(const float4*)(g_h + (size_t)p0.x * H + fl * 4);
        float4 v1 = *(const float4*)(g_h + (size_t)p1.x * H + fl * 4);
        float n0 = __int_as_float(p0.y);
        float n1 = __int_as_float(p1.y);
        acc.x += v0.x * n0; acc.y += v0.y * n0; acc.z += v0.z * n0; acc.w += v0.w * n0;
        acc.x += v1.x * n1; acc.y += v1.y * n1; acc.z += v1.z * n1; acc.w += v1.w * n1;
    }
    if (e < end) {
        int2 p = g_csr[e];
        float nm = __int_as_float(p.y);
        float4 v = *(const float4*)(g_h + (size_t)p.x * H + fl * 4);
        acc.x += v.x * nm; acc.y += v.y * nm; acc.z += v.z * nm; acc.w += v.w * nm;
    }
    float* dst;
    if (FINAL) {
        float4 bb = *(const float4*)(bias + fl * 4);
        acc.x += bb.x; acc.y += bb.y; acc.z += bb.z; acc.w += bb.w;
        dst = zout;
    } else {
        dst = g_agg;
    }
    *(float4*)(dst + (size_t)node * H + fl * 4) = acc;
}

#define DEC_E 128
#define SEFS  132
__global__ void k_decode(const float* __restrict__ z, const void* __restrict__ eli,
                         const float* __restrict__ W1, const float* __restrict__ b1,
                         const float* __restrict__ W2, const float* __restrict__ b2,
                         float* __restrict__ out, int nE, int nNodes) {
    __shared__ float sW1[64 * 64];
    __shared__ float sefT[64][SEFS];
    __shared__ float sred[8][DEC_E];
    __shared__ float sb1[64], sw2[64];

    int tid = threadIdx.x;
    for (int i = tid; i < 64 * 64; i += 128) sW1[i] = W1[i];
    if (tid < 64) { sb1[tid] = b1[tid]; sw2[tid] = W2[tid]; }

    int is64 = g_is64;
    int e0 = blockIdx.x * DEC_E;

    {
        int eg_ = e0 + tid;
        bool valid = eg_ < nE;
        int sidx = 0, didx = 0;
        if (valid) {
            sidx = load_idx(eli, (size_t)eg_, is64, nNodes);
            didx = load_idx(eli, (size_t)nE + eg_, is64, nNodes);
        }
        #pragma unroll
        for (int q = 0; q < 8; q++) {
            float4 v = valid ? *(const float4*)(z + (size_t)sidx * OUTD + q * 4)
                             : make_float4(0.f, 0.f, 0.f, 0.f);
            sefT[q * 4 + 0][tid] = v.x; sefT[q * 4 + 1][tid] = v.y;
            sefT[q * 4 + 2][tid] = v.z; sefT[q * 4 + 3][tid] = v.w;
        }
        #pragma unroll
        for (int q = 0; q < 8; q++) {
            float4 v = valid ? *(const float4*)(z + (size_t)didx * OUTD + q * 4)
                             : make_float4(0.f, 0.f, 0.f, 0.f);
            sefT[32 + q * 4 + 0][tid] = v.x; sefT[32 + q * 4 + 1][tid] = v.y;
            sefT[32 + q * 4 + 2][tid] = v.z; sefT[32 + q * 4 + 3][tid] = v.w;
        }
    }
    __syncthreads();

    int jg = tid & 7;
    int eg = tid >> 3;

    unsigned long long acc2[8][4];
    {
        const float2* bb = (const float2*)&sb1[jg * 8];
        unsigned long long c0 = pack2(bb[0].x, bb[0].y);
        unsigned long long c1 = pack2(bb[1].x, bb[1].y);
        unsigned long long c2 = pack2(bb[2].x, bb[2].y);
        unsigned long long c3 = pack2(bb[3].x, bb[3].y);
        #pragma unroll
        for (int e = 0; e < 8; e++) {
            acc2[e][0] = c0; acc2[e][1] = c1; acc2[e][2] = c2; acc2[e][3] = c3;
        }
    }

    #pragma unroll 4
    for (int k = 0; k < 64; k++) {
        float4 a0 = *(const float4*)&sefT[k][eg * 8];
        float4 a1 = *(const float4*)&sefT[k][eg * 8 + 4];
        const float2* wr = (const float2*)&sW1[k * 64 + jg * 8];
        unsigned long long w0 = pack2(wr[0].x, wr[0].y);
        unsigned long long w1 = pack2(wr[1].x, wr[1].y);
        unsigned long long w2 = pack2(wr[2].x, wr[2].y);
        unsigned long long w3 = pack2(wr[3].x, wr[3].y);
        float av[8] = {a0.x, a0.y, a0.z, a0.w, a1.x, a1.y, a1.z, a1.w};
        #pragma unroll
        for (int e = 0; e < 8; e++) {
            unsigned long long x2 = pack2(av[e], av[e]);
            acc2[e][0] = fma2(x2, w0, acc2[e][0]);
            acc2[e][1] = fma2(x2, w1, acc2[e][1]);
            acc2[e][2] = fma2(x2, w2, acc2[e][2]);
            acc2[e][3] = fma2(x2, w3, acc2[e][3]);
        }
    }

    {
        float w2v[8];
        #pragma unroll
        for (int j = 0; j < 8; j++) w2v[j] = sw2[jg * 8 + j];
        #pragma unroll
        for (int e = 0; e < 8; e++) {
            float p = 0.f;
            #pragma unroll
            for (int jj = 0; jj < 4; jj++) {
                float2 v = unpack2(acc2[e][jj]);
                p += fmaxf(v.x, 0.f) * w2v[jj * 2] + fmaxf(v.y, 0.f) * w2v[jj * 2 + 1];
            }
            sred[jg][eg * 8 + e] = p;
        }
    }
    __syncthreads();

    {
        float t = 0.f;
        #pragma unroll
        for (int j = 0; j < 8; j++) t += sred[j][tid];
        int eg_ = e0 + tid;
        if (eg_ < nE) out[eg_] = t + b2[0];
    }
}

extern "C" void kernel_launch(void* const* d_in, const int* in_sizes, int n_in,
                              void* d_out, int out_size) {
    const float* x    = (const float*)d_in[0];
    const void*  ei   = d_in[1];
    const void*  eli  = d_in[2];
    const float* W1   = (const float*)d_in[3];
    const float* b1   = (const float*)d_in[4];
    const float* W2   = (const float*)d_in[5];
    const float* b2   = (const float*)d_in[6];
    const float* W3   = (const float*)d_in[7];
    const float* b3   = (const float*)d_in[8];
    const float* lpW1 = (const float*)d_in[9];
    const float* lpb1 = (const float*)d_in[10];
    const float* lpW2 = (const float*)d_in[11];
    const float* lpb2 = (const float*)d_in[12];
    float* out = (float*)d_out;

    int N  = in_sizes[0] / FIN;
    int E  = in_sizes[1] / 2;
    int EL = in_sizes[2] / 2;

    const int T = 256;
    int nBlkN = (N + T - 1) / T;
    int nBlkE = (E + T - 1) / T;
    int scanBlocks = (N + 1023) / 1024;

    k_detect<<<1, 256>>>((const int*)ei);
    k_zero_cnt<<<nBlkN, T>>>(N);
    k_count<<<nBlkE, T>>>(ei, E, N);
    k_scan1<<<scanBlocks, 1024>>>(N);
    k_scan2<<<1, 128>>>(N);
    k_scan3<<<nBlkN, T>>>(N);
    k_fill<<<nBlkE, T>>>(ei, E, N);

    int gemmBlocks = (N + 127) / 128;
    auto aggGrid = [&](int nodesPerWarp) {
        int warps = (N + nodesPerWarp - 1) / nodesPerWarp;
        return (warps * 32 + T - 1) / T;
    };

    float* zout = out + EL;

    k_gemm<FIN, HID, false, false><<<gemmBlocks, 128>>>(x, nullptr, W1, N);
    k_aggregate<HID, false><<<aggGrid(2), T>>>(N, nullptr, nullptr);

    k_gemm<HID, HID, true, true><<<gemmBlocks, 128>>>(nullptr, b1, W2, N);
    k_aggregate<HID, false><<<aggGrid(2), T>>>(N, nullptr, nullptr);

    k_gemm<HID, OUTD, true, true><<<gemmBlocks, 64>>>(nullptr, b2, W3, N);
    k_aggregate<OUTD, true><<<aggGrid(4), T>>>(N, b3, zout);

    int decBlocks = (EL + DEC_E - 1) / DEC_E;
    k_decode<<<decBlocks, 128>>>(zout, eli, lpW1, lpb1, lpW2, lpb2, out, EL, N);
}

// round 7
// speedup vs baseline: 3.2391x; 1.1928x over previous
#include <cuda_runtime.h>
#include <cuda_bf16.h>
#include <cstdint>

#define N_MAX   100000
#define E_MAX   3200000
#define FIN     128
#define HID     64
#define OUTD    32
#define SCAN_B  ((N_MAX + 1023) / 1024)   // 98

__device__ __align__(16) float g_h  [(size_t)N_MAX * HID];
__device__ __align__(16) float g_agg[(size_t)N_MAX * HID];
__device__ int   g_cnt   [N_MAX];
__device__ float g_dinv  [N_MAX];
__device__ int   g_rowptr[N_MAX + 1];
__device__ int   g_cursor[N_MAX];
__device__ int   g_bsum  [SCAN_B];
__device__ int   g_boff  [SCAN_B];
__device__ __align__(8) int2 g_csr[E_MAX];
__device__ int   g_is64;

__device__ __forceinline__ unsigned long long fma2(unsigned long long a,
                                                   unsigned long long b,
                                                   unsigned long long c) {
    unsigned long long d;
    asm("fma.rn.f32x2 %0, %1, %2, %3;" : "=l"(d) : "l"(a), "l"(b), "l"(c));
    return d;
}
__device__ __forceinline__ unsigned long long pack2(float lo, float hi) {
    unsigned long long r;
    asm("mov.b64 %0, {%1, %2};" : "=l"(r) : "f"(lo), "f"(hi));
    return r;
}
__device__ __forceinline__ float2 unpack2(unsigned long long v) {
    float2 r;
    asm("mov.b64 {%0, %1}, %2;" : "=f"(r.x), "=f"(r.y) : "l"(v));
    return r;
}

__global__ void k_detect(const int* __restrict__ raw) {
    __shared__ int s_nz;
    if (threadIdx.x == 0) s_nz = 0;
    __syncthreads();
    int nz = 0;
    for (int i = threadIdx.x; i < 512; i += blockDim.x)
        nz |= raw[2 * i + 1];
    if (nz) atomicOr(&s_nz, 1);
    __syncthreads();
    if (threadIdx.x == 0) g_is64 = (s_nz == 0) ? 1 : 0;
}

__device__ __forceinline__ int load_idx(const void* buf, size_t e, int is64, int n) {
    int v;
    if (is64) v = (int)((const long long*)buf)[e];
    else      v = ((const int*)buf)[e];
    if ((unsigned)v >= (unsigned)n) v = 0;
    return v;
}

__global__ void k_zero_cnt(int n) {
    int i = blockIdx.x * blockDim.x + threadIdx.x;
    if (i < n) g_cnt[i] = 0;
}

__global__ void k_count(const void* __restrict__ ei, int nE, int n) {
    int e = blockIdx.x * blockDim.x + threadIdx.x;
    if (e >= nE) return;
    int is64 = g_is64;
    int c = load_idx(ei, (size_t)nE + e, is64, n);
    atomicAdd(&g_cnt[c], 1);
}

__global__ void k_scan1(int n) {
    __shared__ int sh[1024];
    int tid = threadIdx.x;
    int i = blockIdx.x * 1024 + tid;
    int v = (i < n) ? g_cnt[i] : 0;
    if (i < n) g_dinv[i] = rsqrtf((float)v + 1.0f);
    sh[tid] = v;
    __syncthreads();
    #pragma unroll
    for (int off = 1; off < 1024; off <<= 1) {
        int t = (tid >= off) ? sh[tid - off] : 0;
        __syncthreads();
        sh[tid] += t;
        __syncthreads();
    }
    if (i < n) g_rowptr[i] = sh[tid] - v;
    if (tid == 1023) g_bsum[blockIdx.x] = sh[1023];
}

__global__ void k_scan2(int n) {
    __shared__ int sh[128];
    int tid = threadIdx.x;
    int v = (tid < SCAN_B) ? g_bsum[tid] : 0;
    sh[tid] = v;
    __syncthreads();
    #pragma unroll
    for (int off = 1; off < 128; off <<= 1) {
        int t = (tid >= off) ? sh[tid - off] : 0;
        __syncthreads();
        sh[tid] += t;
        __syncthreads();
    }
    if (tid < SCAN_B) g_boff[tid] = sh[tid] - v;
    if (tid == 127) g_rowptr[n] = sh[127];
}

__global__ void k_scan3(int n) {
    int i = blockIdx.x * blockDim.x + threadIdx.x;
    if (i >= n) return;
    int r = g_rowptr[i] + g_boff[i >> 10];
    g_rowptr[i] = r;
    g_cursor[i] = r;
}

__global__ void k_fill(const void* __restrict__ ei, int nE, int n) {
    int e = blockIdx.x * blockDim.x + threadIdx.x;
    if (e >= nE) return;
    int is64 = g_is64;
    int r = load_idx(ei, (size_t)e, is64, n);
    int c = load_idx(ei, (size_t)nE + e, is64, n);
    float nm = g_dinv[r] * g_dinv[c];
    int pos = atomicAdd(&g_cursor[c], 1);
    if (pos >= 0 && pos < E_MAX)
        g_csr[pos] = make_int2(r, __float_as_int(nm));
}

// ---------------- register-tiled GEMM ----------------
// SRC_AGG: read g_agg, else Xext. DST_AGG: write g_agg, else g_h.
template<int K, int M, bool RELU, bool SRC_AGG, bool DST_AGG>
__global__ void k_gemm(const float* __restrict__ Xext,
                       const float* __restrict__ Bk,
                       const float* __restrict__ W, int n) {
    constexpr int KC = (K < 64) ? K : 64;
    constexpr int JG = M / 8;
    constexpr int THREADS = 16 * JG;
    constexpr int XS = 132;
    __shared__ float sW[KC * M];
    __shared__ float sXT[KC][XS];

    int tid = threadIdx.x;
    int jg  = tid & (JG - 1);
    int ng  = tid / JG;
    int n0  = blockIdx.x * 128;

    unsigned long long acc2[8][4];
    #pragma unroll
    for (int e = 0; e < 8; e++)
        #pragma unroll
        for (int jj = 0; jj < 4; jj++) acc2[e][jj] = 0ull;

    const float* src = SRC_AGG ? (const float*)g_agg : Xext;

    for (int kc = 0; kc < K; kc += KC) {
        for (int i = tid; i < KC * M; i += THREADS)
            sW[i] = W[(size_t)kc * M + i];
        for (int nl = tid; nl < 128; nl += THREADS) {
            int node = n0 + nl;
            #pragma unroll
            for (int q = 0; q < KC / 4; q++) {
                float4 v = make_float4(0.f, 0.f, 0.f, 0.f);
                if (node < n) {
                    v = *(const float4*)(src + (size_t)node * K + kc + q * 4);
                    if (RELU) {
                        v.x = fmaxf(v.x + Bk[kc + q * 4 + 0], 0.f);
                        v.y = fmaxf(v.y + Bk[kc + q * 4 + 1], 0.f);
                        v.z = fmaxf(v.z + Bk[kc + q * 4 + 2], 0.f);
                        v.w = fmaxf(v.w + Bk[kc + q * 4 + 3], 0.f);
                    }
                }
                sXT[q * 4 + 0][nl] = v.x;
                sXT[q * 4 + 1][nl] = v.y;
                sXT[q * 4 + 2][nl] = v.z;
                sXT[q * 4 + 3][nl] = v.w;
            }
        }
        __syncthreads();

        #pragma unroll 4
        for (int k = 0; k < KC; k++) {
            float4 a0 = *(const float4*)&sXT[k][ng * 8];
            float4 a1 = *(const float4*)&sXT[k][ng * 8 + 4];
            const float2* wr = (const float2*)&sW[k * M + jg * 8];
            unsigned long long w0 = pack2(wr[0].x, wr[0].y);
            unsigned long long w1 = pack2(wr[1].x, wr[1].y);
            unsigned long long w2 = pack2(wr[2].x, wr[2].y);
            unsigned long long w3 = pack2(wr[3].x, wr[3].y);
            float av[8] = {a0.x, a0.y, a0.z, a0.w, a1.x, a1.y, a1.z, a1.w};
            #pragma unroll
            for (int e = 0; e < 8; e++) {
                unsigned long long x2 = pack2(av[e], av[e]);
                acc2[e][0] = fma2(x2, w0, acc2[e][0]);
                acc2[e][1] = fma2(x2, w1, acc2[e][1]);
                acc2[e][2] = fma2(x2, w2, acc2[e][2]);
                acc2[e][3] = fma2(x2, w3, acc2[e][3]);
            }
        }
        __syncthreads();
    }

    float* outbuf = DST_AGG ? (float*)g_agg : (float*)g_h;
    #pragma unroll
    for (int e = 0; e < 8; e++) {
        int node = n0 + ng * 8 + e;
        if (node < n) {
            float* dst = outbuf + (size_t)node * M + jg * 8;
            #pragma unroll
            for (int jj = 0; jj < 4; jj++)
                *(float2*)(dst + jj * 2) = unpack2(acc2[e][jj]);
        }
    }
}

// FINAL=true: dst = zout with +bias; else dst = g_agg
template<int H, bool FINAL>
__global__ void k_aggregate(int n, const float* __restrict__ bias,
                            float* __restrict__ zout) {
    constexpr int LPN = H / 4;
    constexpr int NPW = 32 / LPN;
    int gw   = (blockIdx.x * blockDim.x + threadIdx.x) >> 5;
    int lane = threadIdx.x & 31;
    int node = gw * NPW + lane / LPN;
    int fl   = lane % LPN;
    if (node >= n) return;

    float d = g_dinv[node];
    float s = d * d;
    float4 acc = *(const float4*)(g_h + (size_t)node * H + fl * 4);
    acc.x *= s; acc.y *= s; acc.z *= s; acc.w *= s;

    int beg = g_rowptr[node];
    int end = g_rowptr[node + 1];
    int e = beg;
    for (; e + 1 < end; e += 2) {
        int2 p0 = g_csr[e];
        int2 p1 = g_csr[e + 1];
        float4 v0 = *(const float4*)(g_h + (size_t)p0.x * H + fl * 4);
        float4 v1 = *(const float4*)(g_h + (size_t)p1.x * H + fl * 4);
        float n0 = __int_as_float(p0.y);
        float n1 = __int_as_float(p1.y);
        acc.x += v0.x * n0; acc.y += v0.y * n0; acc.z += v0.z * n0; acc.w += v0.w * n0;
        acc.x += v1.x * n1; acc.y += v1.y * n1; acc.z += v1.z * n1; acc.w += v1.w * n1;
    }
    if (e < end) {
        int2 p = g_csr[e];
        float nm = __int_as_float(p.y);
        float4 v = *(const float4*)(g_h + (size_t)p.x * H + fl * 4);
        acc.x += v.x * nm; acc.y += v.y * nm; acc.z += v.z * nm; acc.w += v.w * nm;
    }
    float* dst;
    if (FINAL) {
        float4 bb = *(const float4*)(bias + fl * 4);
        acc.x += bb.x; acc.y += bb.y; acc.z += bb.z; acc.w += bb.w;
        dst = zout;
    } else {
        dst = g_agg;
    }
    *(float4*)(dst + (size_t)node * H + fl * 4) = acc;
}

// ---------------- decoder-lite: out[e] = relu(u[src]+v[dst]+b1) . w2 + b2 ----------------
// u in g_h, v in g_agg (both [N, 64]). 16 lanes per edge, float4 per lane, 2 edges/warp.
__global__ void k_decode_lite(const void* __restrict__ eli,
                              const float* __restrict__ b1,
                              const float* __restrict__ w2,
                              const float* __restrict__ b2,
                              float* __restrict__ out, int nE, int nNodes) {
    int gw   = (blockIdx.x * blockDim.x + threadIdx.x) >> 5;
    int lane = threadIdx.x & 31;
    int sub  = lane >> 4;        // edge within warp (0/1)
    int fl   = lane & 15;        // float4 index within edge

    int e = gw * 2 + sub;
    if (e >= nE) return;

    int is64 = g_is64;
    int src = load_idx(eli, (size_t)e, is64, nNodes);
    int dst = load_idx(eli, (size_t)nE + e, is64, nNodes);

    float4 uu = *(const float4*)(g_h   + (size_t)src * HID + fl * 4);
    float4 vv = *(const float4*)(g_agg + (size_t)dst * HID + fl * 4);
    float4 bb = *(const float4*)(b1 + fl * 4);
    float4 ww = *(const float4*)(w2 + fl * 4);

    float p = fmaxf(uu.x + vv.x + bb.x, 0.f) * ww.x
            + fmaxf(uu.y + vv.y + bb.y, 0.f) * ww.y
            + fmaxf(uu.z + vv.z + bb.z, 0.f) * ww.z
            + fmaxf(uu.w + vv.w + bb.w, 0.f) * ww.w;

    p += __shfl_down_sync(0xffffffffu, p, 8, 16);
    p += __shfl_down_sync(0xffffffffu, p, 4, 16);
    p += __shfl_down_sync(0xffffffffu, p, 2, 16);
    p += __shfl_down_sync(0xffffffffu, p, 1, 16);

    if (fl == 0) out[e] = p + b2[0];
}

extern "C" void kernel_launch(void* const* d_in, const int* in_sizes, int n_in,
                              void* d_out, int out_size) {
    const float* x    = (const float*)d_in[0];
    const void*  ei   = d_in[1];
    const void*  eli  = d_in[2];
    const float* W1   = (const float*)d_in[3];
    const float* b1   = (const float*)d_in[4];
    const float* W2   = (const float*)d_in[5];
    const float* b2   = (const float*)d_in[6];
    const float* W3   = (const float*)d_in[7];
    const float* b3   = (const float*)d_in[8];
    const float* lpW1 = (const float*)d_in[9];
    const float* lpb1 = (const float*)d_in[10];
    const float* lpW2 = (const float*)d_in[11];
    const float* lpb2 = (const float*)d_in[12];
    float* out = (float*)d_out;

    int N  = in_sizes[0] / FIN;
    int E  = in_sizes[1] / 2;
    int EL = in_sizes[2] / 2;

    const int T = 256;
    int nBlkN = (N + T - 1) / T;
    int nBlkE = (E + T - 1) / T;
    int scanBlocks = (N + 1023) / 1024;

    k_detect<<<1, 256>>>((const int*)ei);
    k_zero_cnt<<<nBlkN, T>>>(N);
    k_count<<<nBlkE, T>>>(ei, E, N);
    k_scan1<<<scanBlocks, 1024>>>(N);
    k_scan2<<<1, 128>>>(N);
    k_scan3<<<nBlkN, T>>>(N);
    k_fill<<<nBlkE, T>>>(ei, E, N);

    int gemmBlocks = (N + 127) / 128;
    auto aggGrid = [&](int nodesPerWarp) {
        int warps = (N + nodesPerWarp - 1) / nodesPerWarp;
        return (warps * 32 + T - 1) / T;
    };

    float* zout = out + EL;

    // encoder
    k_gemm<FIN, HID, false, false, false><<<gemmBlocks, 128>>>(x, nullptr, W1, N);
    k_aggregate<HID, false><<<aggGrid(2), T>>>(N, nullptr, nullptr);

    k_gemm<HID, HID, true, true, false><<<gemmBlocks, 128>>>(nullptr, b1, W2, N);
    k_aggregate<HID, false><<<aggGrid(2), T>>>(N, nullptr, nullptr);

    k_gemm<HID, OUTD, true, true, false><<<gemmBlocks, 64>>>(nullptr, b2, W3, N);
    k_aggregate<OUTD, true><<<aggGrid(4), T>>>(N, b3, zout);

    // decoder precompute: u = z @ lpW1[0:32,:], v = z @ lpW1[32:64,:]
    k_gemm<OUTD, HID, false, false, false><<<gemmBlocks, 128>>>(zout, nullptr, lpW1, N);
    k_gemm<OUTD, HID, false, false, true ><<<gemmBlocks, 128>>>(zout, nullptr, lpW1 + OUTD * HID, N);

    // decoder-lite: 2 edges per warp
    int warpsD = (EL + 1) / 2;
    int decBlocks = (warpsD * 32 + T - 1) / T;
    k_decode_lite<<<decBlocks, T>>>(eli, lpb1, lpW2, lpb2, out, EL, N);
}

// round 8
// speedup vs baseline: 3.6312x; 1.1210x over previous
#include <cuda_runtime.h>
#include <cuda_fp16.h>
#include <cstdint>

#define N_MAX   100000
#define E_MAX   3200000
#define FIN     128
#define HID     64
#define OUTD    32
#define SCAN_B  ((N_MAX + 1023) / 1024)   // 98

__device__ __align__(16) float  g_h  [(size_t)N_MAX * HID];   // fp32 h / u
__device__ __align__(16) float  g_agg[(size_t)N_MAX * HID];   // fp32 agg / v
__device__ __align__(16) __half g_hh [(size_t)N_MAX * HID];   // fp16 h (layers 1-2)
__device__ int   g_cnt   [N_MAX];
__device__ float g_dinv  [N_MAX];
__device__ int   g_rowptr[N_MAX + 1];
__device__ int   g_cursor[N_MAX];
__device__ int   g_bsum  [SCAN_B];
__device__ int   g_boff  [SCAN_B];
__device__ __align__(8) int2 g_csr[E_MAX];
__device__ int   g_is64;

// output modes for k_gemm
#define OM_F32   0
#define OM_H16   1
#define OM_SPLIT 2

__device__ __forceinline__ unsigned long long fma2(unsigned long long a,
                                                   unsigned long long b,
                                                   unsigned long long c) {
    unsigned long long d;
    asm("fma.rn.f32x2 %0, %1, %2, %3;" : "=l"(d) : "l"(a), "l"(b), "l"(c));
    return d;
}
__device__ __forceinline__ unsigned long long pack2(float lo, float hi) {
    unsigned long long r;
    asm("mov.b64 %0, {%1, %2};" : "=l"(r) : "f"(lo), "f"(hi));
    return r;
}
__device__ __forceinline__ float2 unpack2(unsigned long long v) {
    float2 r;
    asm("mov.b64 {%0, %1}, %2;" : "=f"(r.x), "=f"(r.y) : "l"(v));
    return r;
}
__device__ __forceinline__ void h16x8_to_f32(uint4 r, float* v) {
    const __half2* h = (const __half2*)&r;
    float2 f0 = __half22float2(h[0]);
    float2 f1 = __half22float2(h[1]);
    float2 f2 = __half22float2(h[2]);
    float2 f3 = __half22float2(h[3]);
    v[0] = f0.x; v[1] = f0.y; v[2] = f1.x; v[3] = f1.y;
    v[4] = f2.x; v[5] = f2.y; v[6] = f3.x; v[7] = f3.y;
}

__global__ void k_detect(const int* __restrict__ raw) {
    __shared__ int s_nz;
    if (threadIdx.x == 0) s_nz = 0;
    __syncthreads();
    int nz = 0;
    for (int i = threadIdx.x; i < 512; i += blockDim.x)
        nz |= raw[2 * i + 1];
    if (nz) atomicOr(&s_nz, 1);
    __syncthreads();
    if (threadIdx.x == 0) g_is64 = (s_nz == 0) ? 1 : 0;
}

__device__ __forceinline__ int load_idx(const void* buf, size_t e, int is64, int n) {
    int v;
    if (is64) v = (int)((const long long*)buf)[e];
    else      v = ((const int*)buf)[e];
    if ((unsigned)v >= (unsigned)n) v = 0;
    return v;
}

__global__ void k_zero_cnt(int n) {
    int i = blockIdx.x * blockDim.x + threadIdx.x;
    if (i < n) g_cnt[i] = 0;
}

__global__ void k_count(const void* __restrict__ ei, int nE, int n) {
    int e = blockIdx.x * blockDim.x + threadIdx.x;
    if (e >= nE) return;
    int is64 = g_is64;
    int c = load_idx(ei, (size_t)nE + e, is64, n);
    atomicAdd(&g_cnt[c], 1);
}

__global__ void k_scan1(int n) {
    __shared__ int sh[1024];
    int tid = threadIdx.x;
    int i = blockIdx.x * 1024 + tid;
    int v = (i < n) ? g_cnt[i] : 0;
    if (i < n) g_dinv[i] = rsqrtf((float)v + 1.0f);
    sh[tid] = v;
    __syncthreads();
    #pragma unroll
    for (int off = 1; off < 1024; off <<= 1) {
        int t = (tid >= off) ? sh[tid - off] : 0;
        __syncthreads();
        sh[tid] += t;
        __syncthreads();
    }
    if (i < n) g_rowptr[i] = sh[tid] - v;
    if (tid == 1023) g_bsum[blockIdx.x] = sh[1023];
}

__global__ void k_scan2(int n) {
    __shared__ int sh[128];
    int tid = threadIdx.x;
    int v = (tid < SCAN_B) ? g_bsum[tid] : 0;
    sh[tid] = v;
    __syncthreads();
    #pragma unroll
    for (int off = 1; off < 128; off <<= 1) {
        int t = (tid >= off) ? sh[tid - off] : 0;
        __syncthreads();
        sh[tid] += t;
        __syncthreads();
    }
    if (tid < SCAN_B) g_boff[tid] = sh[tid] - v;
    if (tid == 127) g_rowptr[n] = sh[127];
}

__global__ void k_scan3(int n) {
    int i = blockIdx.x * blockDim.x + threadIdx.x;
    if (i >= n) return;
    int r = g_rowptr[i] + g_boff[i >> 10];
    g_rowptr[i] = r;
    g_cursor[i] = r;
}

__global__ void k_fill(const void* __restrict__ ei, int nE, int n) {
    int e = blockIdx.x * blockDim.x + threadIdx.x;
    if (e >= nE) return;
    int is64 = g_is64;
    int r = load_idx(ei, (size_t)e, is64, n);
    int c = load_idx(ei, (size_t)nE + e, is64, n);
    float nm = g_dinv[r] * g_dinv[c];
    int pos = atomicAdd(&g_cursor[c], 1);
    if (pos >= 0 && pos < E_MAX)
        g_csr[pos] = make_int2(r, __float_as_int(nm));
}

// ---------------- register-tiled GEMM ----------------
// OMODE: OM_F32 -> g_h fp32 | OM_H16 -> g_hh fp16 | OM_SPLIT -> cols 0-63 g_h, 64-127 g_agg
// OM_SPLIT also stages W as [lpW1_top | lpW1_bot] (W is [2*K, 64], M must be 128).
template<int K, int M, bool RELU, bool SRC_AGG, int OMODE>
__global__ void k_gemm(const float* __restrict__ Xext,
                       const float* __restrict__ Bk,
                       const float* __restrict__ W, int n) {
    constexpr int KC = (K < 64) ? K : 64;
    constexpr int JG = M / 8;
    constexpr int THREADS = 16 * JG;
    constexpr int XS = 132;
    __shared__ float sW[KC * M];
    __shared__ float sXT[KC][XS];

    int tid = threadIdx.x;
    int jg  = tid & (JG - 1);
    int ng  = tid / JG;
    int n0  = blockIdx.x * 128;

    unsigned long long acc2[8][4];
    #pragma unroll
    for (int e = 0; e < 8; e++)
        #pragma unroll
        for (int jj = 0; jj < 4; jj++) acc2[e][jj] = 0ull;

    const float* src = SRC_AGG ? (const float*)g_agg : Xext;

    for (int kc = 0; kc < K; kc += KC) {
        if (OMODE == OM_SPLIT) {
            // W is [2K, 64]; columns j<64 from row k, j>=64 from row k+K
            for (int i = tid; i < KC * M; i += THREADS) {
                int k = i / M, j = i % M;
                sW[i] = (j < 64) ? W[(size_t)(kc + k) * 64 + j]
                                 : W[(size_t)(kc + k + K) * 64 + (j - 64)];
            }
        } else {
            for (int i = tid; i < KC * M; i += THREADS)
                sW[i] = W[(size_t)kc * M + i];
        }
        for (int nl = tid; nl < 128; nl += THREADS) {
            int node = n0 + nl;
            #pragma unroll
            for (int q = 0; q < KC / 4; q++) {
                float4 v = make_float4(0.f, 0.f, 0.f, 0.f);
                if (node < n) {
                    v = *(const float4*)(src + (size_t)node * K + kc + q * 4);
                    if (RELU) {
                        v.x = fmaxf(v.x + Bk[kc + q * 4 + 0], 0.f);
                        v.y = fmaxf(v.y + Bk[kc + q * 4 + 1], 0.f);
                        v.z = fmaxf(v.z + Bk[kc + q * 4 + 2], 0.f);
                        v.w = fmaxf(v.w + Bk[kc + q * 4 + 3], 0.f);
                    }
                }
                sXT[q * 4 + 0][nl] = v.x;
                sXT[q * 4 + 1][nl] = v.y;
                sXT[q * 4 + 2][nl] = v.z;
                sXT[q * 4 + 3][nl] = v.w;
            }
        }
        __syncthreads();

        #pragma unroll 4
        for (int k = 0; k < KC; k++) {
            float4 a0 = *(const float4*)&sXT[k][ng * 8];
            float4 a1 = *(const float4*)&sXT[k][ng * 8 + 4];
            const float2* wr = (const float2*)&sW[k * M + jg * 8];
            unsigned long long w0 = pack2(wr[0].x, wr[0].y);
            unsigned long long w1 = pack2(wr[1].x, wr[1].y);
            unsigned long long w2 = pack2(wr[2].x, wr[2].y);
            unsigned long long w3 = pack2(wr[3].x, wr[3].y);
            float av[8] = {a0.x, a0.y, a0.z, a0.w, a1.x, a1.y, a1.z, a1.w};
            #pragma unroll
            for (int e = 0; e < 8; e++) {
                unsigned long long x2 = pack2(av[e], av[e]);
                acc2[e][0] = fma2(x2, w0, acc2[e][0]);
                acc2[e][1] = fma2(x2, w1, acc2[e][1]);
                acc2[e][2] = fma2(x2, w2, acc2[e][2]);
                acc2[e][3] = fma2(x2, w3, acc2[e][3]);
            }
        }
        __syncthreads();
    }

    #pragma unroll
    for (int e = 0; e < 8; e++) {
        int node = n0 + ng * 8 + e;
        if (node >= n) continue;
        if (OMODE == OM_H16) {
            uint4 pkt;
            __half2* ph = (__half2*)&pkt;
            #pragma unroll
            for (int jj = 0; jj < 4; jj++) {
                float2 f = unpack2(acc2[e][jj]);
                ph[jj] = __floats2half2_rn(f.x, f.y);
            }
            *(uint4*)(g_hh + (size_t)node * M + jg * 8) = pkt;
        } else if (OMODE == OM_SPLIT) {
            float* dst = (jg < 8) ? (g_h   + (size_t)node * 64 + jg * 8)
                                  : (g_agg + (size_t)node * 64 + (jg - 8) * 8);
            #pragma unroll
            for (int jj = 0; jj < 4; jj++)
                *(float2*)(dst + jj * 2) = unpack2(acc2[e][jj]);
        } else {
            float* dst = g_h + (size_t)node * M + jg * 8;
            #pragma unroll
            for (int jj = 0; jj < 4; jj++)
                *(float2*)(dst + jj * 2) = unpack2(acc2[e][jj]);
        }
    }
}

// ---------------- fp16-gather aggregation (H=64, layers 1-2) ----------------
// g_agg[c] = h16[c]*dinv[c]^2 + sum_e h16[src(e)]*norm(e); fp32 accumulate.
// 8 lanes per node, 4 nodes per warp; each lane owns 8 columns (16B fp16 load).
__global__ void k_aggregate_h16(int n) {
    int gw   = (blockIdx.x * blockDim.x + threadIdx.x) >> 5;
    int lane = threadIdx.x & 31;
    int node = gw * 4 + (lane >> 3);
    int fl   = lane & 7;
    if (node >= n) return;

    float d = g_dinv[node];
    float s = d * d;
    float acc[8], v[8];
    uint4 rs = *(const uint4*)(g_hh + (size_t)node * HID + fl * 8);
    h16x8_to_f32(rs, v);
    #pragma unroll
    for (int i = 0; i < 8; i++) acc[i] = v[i] * s;

    int beg = g_rowptr[node];
    int end = g_rowptr[node + 1];
    int e = beg;
    for (; e + 1 < end; e += 2) {
        int2 p0 = g_csr[e];
        int2 p1 = g_csr[e + 1];
        uint4 r0 = *(const uint4*)(g_hh + (size_t)p0.x * HID + fl * 8);
        uint4 r1 = *(const uint4*)(g_hh + (size_t)p1.x * HID + fl * 8);
        float n0 = __int_as_float(p0.y);
        float n1 = __int_as_float(p1.y);
        float v0[8], v1[8];
        h16x8_to_f32(r0, v0);
        h16x8_to_f32(r1, v1);
        #pragma unroll
        for (int i = 0; i < 8; i++) acc[i] += v0[i] * n0;
        #pragma unroll
        for (int i = 0; i < 8; i++) acc[i] += v1[i] * n1;
    }
    if (e < end) {
        int2 p = g_csr[e];
        uint4 r0 = *(const uint4*)(g_hh + (size_t)p.x * HID + fl * 8);
        float nm = __int_as_float(p.y);
        h16x8_to_f32(r0, v);
        #pragma unroll
        for (int i = 0; i < 8; i++) acc[i] += v[i] * nm;
    }
    float* dst = g_agg + (size_t)node * HID + fl * 8;
    *(float4*)(dst)     = make_float4(acc[0], acc[1], acc[2], acc[3]);
    *(float4*)(dst + 4) = make_float4(acc[4], acc[5], acc[6], acc[7]);
}

// ---------------- fp32 aggregation (H=32, final layer; +bias, writes zout) ----------------
__global__ void k_aggregate_final(int n, const float* __restrict__ bias,
                                  float* __restrict__ zout) {
    constexpr int H = OUTD;
    constexpr int LPN = H / 4;       // 8
    constexpr int NPW = 32 / LPN;    // 4
    int gw   = (blockIdx.x * blockDim.x + threadIdx.x) >> 5;
    int lane = threadIdx.x & 31;
    int node = gw * NPW + lane / LPN;
    int fl   = lane % LPN;
    if (node >= n) return;

    float d = g_dinv[node];
    float s = d * d;
    float4 acc = *(const float4*)(g_h + (size_t)node * H + fl * 4);
    acc.x *= s; acc.y *= s; acc.z *= s; acc.w *= s;

    int beg = g_rowptr[node];
    int end = g_rowptr[node + 1];
    int e = beg;
    for (; e + 1 < end; e += 2) {
        int2 p0 = g_csr[e];
        int2 p1 = g_csr[e + 1];
        float4 v0 = *(const float4*)(g_h + (size_t)p0.x * H + fl * 4);
        float4 v1 = *(const float4*)(g_h + (size_t)p1.x * H + fl * 4);
        float n0 = __int_as_float(p0.y);
        float n1 = __int_as_float(p1.y);
        acc.x += v0.x * n0; acc.y += v0.y * n0; acc.z += v0.z * n0; acc.w += v0.w * n0;
        acc.x += v1.x * n1; acc.y += v1.y * n1; acc.z += v1.z * n1; acc.w += v1.w * n1;
    }
    if (e < end) {
        int2 p = g_csr[e];
        float nm = __int_as_float(p.y);
        float4 v = *(const float4*)(g_h + (size_t)p.x * H + fl * 4);
        acc.x += v.x * nm; acc.y += v.y * nm; acc.z += v.z * nm; acc.w += v.w * nm;
    }
    float4 bb = *(const float4*)(bias + fl * 4);
    acc.x += bb.x; acc.y += bb.y; acc.z += bb.z; acc.w += bb.w;
    *(float4*)(zout + (size_t)node * H + fl * 4) = acc;
}

// ---------------- decoder-lite: out[e] = relu(u[src]+v[dst]+b1) . w2 + b2 ----------------
__global__ void k_decode_lite(const void* __restrict__ eli,
                              const float* __restrict__ b1,
                              const float* __restrict__ w2,
                              const float* __restrict__ b2,
                              float* __restrict__ out, int nE, int nNodes) {
    int gw   = (blockIdx.x * blockDim.x + threadIdx.x) >> 5;
    int lane = threadIdx.x & 31;
    int sub  = lane >> 4;
    int fl   = lane & 15;

    int e = gw * 2 + sub;
    if (e >= nE) return;

    int is64 = g_is64;
    int src = load_idx(eli, (size_t)e, is64, nNodes);
    int dst = load_idx(eli, (size_t)nE + e, is64, nNodes);

    float4 uu = *(const float4*)(g_h   + (size_t)src * HID + fl * 4);
    float4 vv = *(const float4*)(g_agg + (size_t)dst * HID + fl * 4);
    float4 bb = *(const float4*)(b1 + fl * 4);
    float4 ww = *(const float4*)(w2 + fl * 4);

    float p = fmaxf(uu.x + vv.x + bb.x, 0.f) * ww.x
            + fmaxf(uu.y + vv.y + bb.y, 0.f) * ww.y
            + fmaxf(uu.z + vv.z + bb.z, 0.f) * ww.z
            + fmaxf(uu.w + vv.w + bb.w, 0.f) * ww.w;

    p += __shfl_down_sync(0xffffffffu, p, 8, 16);
    p += __shfl_down_sync(0xffffffffu, p, 4, 16);
    p += __shfl_down_sync(0xffffffffu, p, 2, 16);
    p += __shfl_down_sync(0xffffffffu, p, 1, 16);

    if (fl == 0) out[e] = p + b2[0];
}

extern "C" void kernel_launch(void* const* d_in, const int* in_sizes, int n_in,
                              void* d_out, int out_size) {
    const float* x    = (const float*)d_in[0];
    const void*  ei   = d_in[1];
    const void*  eli  = d_in[2];
    const float* W1   = (const float*)d_in[3];
    const float* b1   = (const float*)d_in[4];
    const float* W2   = (const float*)d_in[5];
    const float* b2   = (const float*)d_in[6];
    const float* W3   = (const float*)d_in[7];
    const float* b3   = (const float*)d_in[8];
    const float* lpW1 = (const float*)d_in[9];
    const float* lpb1 = (const float*)d_in[10];
    const float* lpW2 = (const float*)d_in[11];
    const float* lpb2 = (const float*)d_in[12];
    float* out = (float*)d_out;

    int N  = in_sizes[0] / FIN;
    int E  = in_sizes[1] / 2;
    int EL = in_sizes[2] / 2;

    const int T = 256;
    int nBlkN = (N + T - 1) / T;
    int nBlkE = (E + T - 1) / T;
    int scanBlocks = (N + 1023) / 1024;

    k_detect<<<1, 256>>>((const int*)ei);
    k_zero_cnt<<<nBlkN, T>>>(N);
    k_count<<<nBlkE, T>>>(ei, E, N);
    k_scan1<<<scanBlocks, 1024>>>(N);
    k_scan2<<<1, 128>>>(N);
    k_scan3<<<nBlkN, T>>>(N);
    k_fill<<<nBlkE, T>>>(ei, E, N);

    int gemmBlocks = (N + 127) / 128;
    int warpsA = (N + 3) / 4;                       // 4 nodes per warp
    int aggBlocks = (warpsA * 32 + T - 1) / T;

    float* zout = out + EL;

    // encoder (layers 1-2 emit fp16 h; aggregation gathers fp16, accumulates fp32)
    k_gemm<FIN, HID, false, false, OM_H16><<<gemmBlocks, 128>>>(x, nullptr, W1, N);
    k_aggregate_h16<<<aggBlocks, T>>>(N);

    k_gemm<HID, HID, true, true, OM_H16><<<gemmBlocks, 128>>>(nullptr, b1, W2, N);
    k_aggregate_h16<<<aggBlocks, T>>>(N);

    // layer 3 fully fp32 (produces output z)
    k_gemm<HID, OUTD, true, true, OM_F32><<<gemmBlocks, 64>>>(nullptr, b2, W3, N);
    k_aggregate_final<<<aggBlocks, T>>>(N, b3, zout);

    // fused decoder precompute: [u|v] = z @ [lpW1_top | lpW1_bot]
    k_gemm<OUTD, 128, false, false, OM_SPLIT><<<gemmBlocks, 256>>>(zout, nullptr, lpW1, N);

    // decoder-lite
    int warpsD = (EL + 1) / 2;
    int decBlocks = (warpsD * 32 + T - 1) / T;
    k_decode_lite<<<decBlocks, T>>>(eli, lpb1, lpW2, lpb2, out, EL, N);
}

// round 9
// speedup vs baseline: 4.4722x; 1.2316x over previous
#include <cuda_runtime.h>
#include <cuda_fp16.h>
#include <cstdint>

#define N_MAX   100000
#define E_MAX   3200000
#define FIN     128
#define HID     64
#define OUTD    32
#define SCAN_B  ((N_MAX + 1023) / 1024)   // 98

__device__ __align__(16) float  g_agg[(size_t)N_MAX * HID];   // fp32 aggregate
__device__ __align__(16) __half g_hh [(size_t)N_MAX * HID];   // fp16 hs / u
__device__ __align__(16) __half g_vv [(size_t)N_MAX * HID];   // fp16 v
__device__ int   g_cnt   [N_MAX];
__device__ float g_dinv  [N_MAX];
__device__ int   g_rowptr[N_MAX + 1];
__device__ int   g_cursor[N_MAX];
__device__ int   g_bsum  [SCAN_B];
__device__ int   g_boff  [SCAN_B];
__device__ int   g_csr   [E_MAX];                             // src only
__device__ int   g_is64;

// output modes for k_gemm
#define OM_H16S    0   // fp16, scaled by dinv[node], -> g_hh
#define OM_SPLIT16 1   // fp16 u -> g_hh, v -> g_vv (M=128, W = [lpW1_top|lpW1_bot])

__device__ __forceinline__ unsigned long long fma2(unsigned long long a,
                                                   unsigned long long b,
                                                   unsigned long long c) {
    unsigned long long d;
    asm("fma.rn.f32x2 %0, %1, %2, %3;" : "=l"(d) : "l"(a), "l"(b), "l"(c));
    return d;
}
__device__ __forceinline__ unsigned long long pack2(float lo, float hi) {
    unsigned long long r;
    asm("mov.b64 %0, {%1, %2};" : "=l"(r) : "f"(lo), "f"(hi));
    return r;
}
__device__ __forceinline__ float2 unpack2(unsigned long long v) {
    float2 r;
    asm("mov.b64 {%0, %1}, %2;" : "=f"(r.x), "=f"(r.y) : "l"(v));
    return r;
}
__device__ __forceinline__ void h16x8_to_f32(uint4 r, float* v) {
    const __half2* h = (const __half2*)&r;
    float2 f0 = __half22float2(h[0]);
    float2 f1 = __half22float2(h[1]);
    float2 f2 = __half22float2(h[2]);
    float2 f3 = __half22float2(h[3]);
    v[0] = f0.x; v[1] = f0.y; v[2] = f1.x; v[3] = f1.y;
    v[4] = f2.x; v[5] = f2.y; v[6] = f3.x; v[7] = f3.y;
}

__global__ void k_detect(const int* __restrict__ raw) {
    __shared__ int s_nz;
    if (threadIdx.x == 0) s_nz = 0;
    __syncthreads();
    int nz = 0;
    for (int i = threadIdx.x; i < 512; i += blockDim.x)
        nz |= raw[2 * i + 1];
    if (nz) atomicOr(&s_nz, 1);
    __syncthreads();
    if (threadIdx.x == 0) g_is64 = (s_nz == 0) ? 1 : 0;
}

__device__ __forceinline__ int load_idx(const void* buf, size_t e, int is64, int n) {
    int v;
    if (is64) v = (int)((const long long*)buf)[e];
    else      v = ((const int*)buf)[e];
    if ((unsigned)v >= (unsigned)n) v = 0;
    return v;
}

__global__ void k_zero_cnt(int n) {
    int i = blockIdx.x * blockDim.x + threadIdx.x;
    if (i < n) g_cnt[i] = 0;
}

__global__ void k_count(const void* __restrict__ ei, int nE, int n) {
    int e = blockIdx.x * blockDim.x + threadIdx.x;
    if (e >= nE) return;
    int is64 = g_is64;
    int c = load_idx(ei, (size_t)nE + e, is64, n);
    atomicAdd(&g_cnt[c], 1);
}

__global__ void k_scan1(int n) {
    __shared__ int sh[1024];
    int tid = threadIdx.x;
    int i = blockIdx.x * 1024 + tid;
    int v = (i < n) ? g_cnt[i] : 0;
    if (i < n) g_dinv[i] = rsqrtf((float)v + 1.0f);
    sh[tid] = v;
    __syncthreads();
    #pragma unroll
    for (int off = 1; off < 1024; off <<= 1) {
        int t = (tid >= off) ? sh[tid - off] : 0;
        __syncthreads();
        sh[tid] += t;
        __syncthreads();
    }
    if (i < n) g_rowptr[i] = sh[tid] - v;
    if (tid == 1023) g_bsum[blockIdx.x] = sh[1023];
}

__global__ void k_scan2(int n) {
    __shared__ int sh[128];
    int tid = threadIdx.x;
    int v = (tid < SCAN_B) ? g_bsum[tid] : 0;
    sh[tid] = v;
    __syncthreads();
    #pragma unroll
    for (int off = 1; off < 128; off <<= 1) {
        int t = (tid >= off) ? sh[tid - off] : 0;
        __syncthreads();
        sh[tid] += t;
        __syncthreads();
    }
    if (tid < SCAN_B) g_boff[tid] = sh[tid] - v;
    if (tid == 127) g_rowptr[n] = sh[127];
}

__global__ void k_scan3(int n) {
    int i = blockIdx.x * blockDim.x + threadIdx.x;
    if (i >= n) return;
    int r = g_rowptr[i] + g_boff[i >> 10];
    g_rowptr[i] = r;
    g_cursor[i] = r;
}

__global__ void k_fill(const void* __restrict__ ei, int nE, int n) {
    int e = blockIdx.x * blockDim.x + threadIdx.x;
    if (e >= nE) return;
    int is64 = g_is64;
    int r = load_idx(ei, (size_t)e, is64, n);
    int c = load_idx(ei, (size_t)nE + e, is64, n);
    int pos = atomicAdd(&g_cursor[c], 1);
    if (pos >= 0 && pos < E_MAX) g_csr[pos] = r;
}

// ---------------- register-tiled GEMM ----------------
// OM_H16S:   out fp16 scaled by dinv[node] into g_hh (layout N x M)
// OM_SPLIT16: M=128, cols 0-63 -> g_hh (u), 64-127 -> g_vv (v), fp16 unscaled;
//             W staged as [lpW1_top | lpW1_bot] from a [2K, 64] source.
template<int K, int M, bool RELU, bool SRC_AGG, int OMODE>
__global__ void k_gemm(const float* __restrict__ Xext,
                       const float* __restrict__ Bk,
                       const float* __restrict__ W, int n) {
    constexpr int KC = (K < 64) ? K : 64;
    constexpr int JG = M / 8;
    constexpr int THREADS = 16 * JG;
    constexpr int XS = 132;
    __shared__ float sW[KC * M];
    __shared__ float sXT[KC][XS];

    int tid = threadIdx.x;
    int jg  = tid & (JG - 1);
    int ng  = tid / JG;
    int n0  = blockIdx.x * 128;

    unsigned long long acc2[8][4];
    #pragma unroll
    for (int e = 0; e < 8; e++)
        #pragma unroll
        for (int jj = 0; jj < 4; jj++) acc2[e][jj] = 0ull;

    const float* src = SRC_AGG ? (const float*)g_agg : Xext;

    for (int kc = 0; kc < K; kc += KC) {
        if (OMODE == OM_SPLIT16) {
            for (int i = tid; i < KC * M; i += THREADS) {
                int k = i / M, j = i % M;
                sW[i] = (j < 64) ? W[(size_t)(kc + k) * 64 + j]
                                 : W[(size_t)(kc + k + K) * 64 + (j - 64)];
            }
        } else {
            for (int i = tid; i < KC * M; i += THREADS)
                sW[i] = W[(size_t)kc * M + i];
        }
        for (int nl = tid; nl < 128; nl += THREADS) {
            int node = n0 + nl;
            #pragma unroll
            for (int q = 0; q < KC / 4; q++) {
                float4 v = make_float4(0.f, 0.f, 0.f, 0.f);
                if (node < n) {
                    v = *(const float4*)(src + (size_t)node * K + kc + q * 4);
                    if (RELU) {
                        v.x = fmaxf(v.x + Bk[kc + q * 4 + 0], 0.f);
                        v.y = fmaxf(v.y + Bk[kc + q * 4 + 1], 0.f);
                        v.z = fmaxf(v.z + Bk[kc + q * 4 + 2], 0.f);
                        v.w = fmaxf(v.w + Bk[kc + q * 4 + 3], 0.f);
                    }
                }
                sXT[q * 4 + 0][nl] = v.x;
                sXT[q * 4 + 1][nl] = v.y;
                sXT[q * 4 + 2][nl] = v.z;
                sXT[q * 4 + 3][nl] = v.w;
            }
        }
        __syncthreads();

        #pragma unroll 4
        for (int k = 0; k < KC; k++) {
            float4 a0 = *(const float4*)&sXT[k][ng * 8];
            float4 a1 = *(const float4*)&sXT[k][ng * 8 + 4];
            const float2* wr = (const float2*)&sW[k * M + jg * 8];
            unsigned long long w0 = pack2(wr[0].x, wr[0].y);
            unsigned long long w1 = pack2(wr[1].x, wr[1].y);
            unsigned long long w2 = pack2(wr[2].x, wr[2].y);
            unsigned long long w3 = pack2(wr[3].x, wr[3].y);
            float av[8] = {a0.x, a0.y, a0.z, a0.w, a1.x, a1.y, a1.z, a1.w};
            #pragma unroll
            for (int e = 0; e < 8; e++) {
                unsigned long long x2 = pack2(av[e], av[e]);
                acc2[e][0] = fma2(x2, w0, acc2[e][0]);
                acc2[e][1] = fma2(x2, w1, acc2[e][1]);
                acc2[e][2] = fma2(x2, w2, acc2[e][2]);
                acc2[e][3] = fma2(x2, w3, acc2[e][3]);
            }
        }
        __syncthreads();
    }

    #pragma unroll
    for (int e = 0; e < 8; e++) {
        int node = n0 + ng * 8 + e;
        if (node >= n) continue;
        uint4 pkt;
        __half2* ph = (__half2*)&pkt;
        if (OMODE == OM_H16S) {
            float dv = g_dinv[node];
            #pragma unroll
            for (int jj = 0; jj < 4; jj++) {
                float2 f = unpack2(acc2[e][jj]);
                ph[jj] = __floats2half2_rn(f.x * dv, f.y * dv);
            }
            *(uint4*)(g_hh + (size_t)node * M + jg * 8) = pkt;
        } else {   // OM_SPLIT16
            #pragma unroll
            for (int jj = 0; jj < 4; jj++) {
                float2 f = unpack2(acc2[e][jj]);
                ph[jj] = __floats2half2_rn(f.x, f.y);
            }
            __half* dst = (jg < 8) ? (g_hh + (size_t)node * 64 + jg * 8)
                                   : (g_vv + (size_t)node * 64 + (jg - 8) * 8);
            *(uint4*)dst = pkt;
        }
    }
}

// ---------------- aggregation over scaled fp16 hs ----------------
// acc = hs[c] + sum_e hs[src(e)];  result = dinv[c] * acc  (+bias when FINAL)
// FINAL writes zout fp32; else writes g_agg fp32.
template<int H, bool FINAL>
__global__ void k_agg16(int n, const float* __restrict__ bias,
                        float* __restrict__ zout) {
    constexpr int LPN = H / 8;       // lanes per node (8 halves = 16B each)
    constexpr int NPW = 32 / LPN;
    int gw   = (blockIdx.x * blockDim.x + threadIdx.x) >> 5;
    int lane = threadIdx.x & 31;
    int node = gw * NPW + lane / LPN;
    int fl   = lane % LPN;
    if (node >= n) return;

    float acc[8], v0[8], v1[8];
    uint4 rs = *(const uint4*)(g_hh + (size_t)node * H + fl * 8);
    h16x8_to_f32(rs, acc);

    int beg = g_rowptr[node];
    int end = g_rowptr[node + 1];
    int e = beg;
    for (; e + 1 < end; e += 2) {
        int s0 = g_csr[e];
        int s1 = g_csr[e + 1];
        uint4 r0 = *(const uint4*)(g_hh + (size_t)s0 * H + fl * 8);
        uint4 r1 = *(const uint4*)(g_hh + (size_t)s1 * H + fl * 8);
        h16x8_to_f32(r0, v0);
        h16x8_to_f32(r1, v1);
        #pragma unroll
        for (int i = 0; i < 8; i++) acc[i] += v0[i];
        #pragma unroll
        for (int i = 0; i < 8; i++) acc[i] += v1[i];
    }
    if (e < end) {
        int s0 = g_csr[e];
        uint4 r0 = *(const uint4*)(g_hh + (size_t)s0 * H + fl * 8);
        h16x8_to_f32(r0, v0);
        #pragma unroll
        for (int i = 0; i < 8; i++) acc[i] += v0[i];
    }

    float dv = g_dinv[node];
    if (FINAL) {
        float* dst = zout + (size_t)node * H + fl * 8;
        float4 b0 = *(const float4*)(bias + fl * 8);
        float4 b1 = *(const float4*)(bias + fl * 8 + 4);
        *(float4*)(dst)     = make_float4(acc[0] * dv + b0.x, acc[1] * dv + b0.y,
                                          acc[2] * dv + b0.z, acc[3] * dv + b0.w);
        *(float4*)(dst + 4) = make_float4(acc[4] * dv + b1.x, acc[5] * dv + b1.y,
                                          acc[6] * dv + b1.z, acc[7] * dv + b1.w);
    } else {
        float* dst = g_agg + (size_t)node * H + fl * 8;
        *(float4*)(dst)     = make_float4(acc[0] * dv, acc[1] * dv, acc[2] * dv, acc[3] * dv);
        *(float4*)(dst + 4) = make_float4(acc[4] * dv, acc[5] * dv, acc[6] * dv, acc[7] * dv);
    }
}

// ---------------- decoder-lite (fp16 u/v): out[e] = relu(u[src]+v[dst]+b1).w2 + b2 ----------------
// 8 lanes per edge (8 halves each), 4 edges per warp.
__global__ void k_decode_lite(const void* __restrict__ eli,
                              const float* __restrict__ b1,
                              const float* __restrict__ w2,
                              const float* __restrict__ b2,
                              float* __restrict__ out, int nE, int nNodes) {
    int gw   = (blockIdx.x * blockDim.x + threadIdx.x) >> 5;
    int lane = threadIdx.x & 31;
    int sub  = lane >> 3;        // edge within warp (0..3)
    int fl   = lane & 7;         // 8-half chunk within edge

    int e = gw * 4 + sub;
    if (e >= nE) return;

    int is64 = g_is64;
    int src = load_idx(eli, (size_t)e, is64, nNodes);
    int dst = load_idx(eli, (size_t)nE + e, is64, nNodes);

    uint4 ru = *(const uint4*)(g_hh + (size_t)src * HID + fl * 8);
    uint4 rv = *(const uint4*)(g_vv + (size_t)dst * HID + fl * 8);
    float uu[8], vv[8];
    h16x8_to_f32(ru, uu);
    h16x8_to_f32(rv, vv);
    float4 b0 = *(const float4*)(b1 + fl * 8);
    float4 b1v = *(const float4*)(b1 + fl * 8 + 4);
    float4 w0 = *(const float4*)(w2 + fl * 8);
    float4 w1 = *(const float4*)(w2 + fl * 8 + 4);
    float bb[8] = {b0.x, b0.y, b0.z, b0.w, b1v.x, b1v.y, b1v.z, b1v.w};
    float ww[8] = {w0.x, w0.y, w0.z, w0.w, w1.x, w1.y, w1.z, w1.w};

    float p = 0.f;
    #pragma unroll
    for (int i = 0; i < 8; i++)
        p += fmaxf(uu[i] + vv[i] + bb[i], 0.f) * ww[i];

    p += __shfl_down_sync(0xffffffffu, p, 4, 8);
    p += __shfl_down_sync(0xffffffffu, p, 2, 8);
    p += __shfl_down_sync(0xffffffffu, p, 1, 8);

    if (fl == 0) out[e] = p + b2[0];
}

extern "C" void kernel_launch(void* const* d_in, const int* in_sizes, int n_in,
                              void* d_out, int out_size) {
    const float* x    = (const float*)d_in[0];
    const void*  ei   = d_in[1];
    const void*  eli  = d_in[2];
    const float* W1   = (const float*)d_in[3];
    const float* b1   = (const float*)d_in[4];
    const float* W2   = (const float*)d_in[5];
    const float* b2   = (const float*)d_in[6];
    const float* W3   = (const float*)d_in[7];
    const float* b3   = (const float*)d_in[8];
    const float* lpW1 = (const float*)d_in[9];
    const float* lpb1 = (const float*)d_in[10];
    const float* lpW2 = (const float*)d_in[11];
    const float* lpb2 = (const float*)d_in[12];
    float* out = (float*)d_out;

    int N  = in_sizes[0] / FIN;
    int E  = in_sizes[1] / 2;
    int EL = in_sizes[2] / 2;

    const int T = 256;
    int nBlkN = (N + T - 1) / T;
    int nBlkE = (E + T - 1) / T;
    int scanBlocks = (N + 1023) / 1024;

    k_detect<<<1, 256>>>((const int*)ei);
    k_zero_cnt<<<nBlkN, T>>>(N);
    k_count<<<nBlkE, T>>>(ei, E, N);
    k_scan1<<<scanBlocks, 1024>>>(N);
    k_scan2<<<1, 128>>>(N);
    k_scan3<<<nBlkN, T>>>(N);
    k_fill<<<nBlkE, T>>>(ei, E, N);

    int gemmBlocks = (N + 127) / 128;
    int warps64 = (N + 3) / 4;                      // H=64: 4 nodes/warp
    int agg64Blocks = (warps64 * 32 + T - 1) / T;
    int warps32 = (N + 7) / 8;                      // H=32: 8 nodes/warp
    int agg32Blocks = (warps32 * 32 + T - 1) / T;

    float* zout = out + EL;

    // encoder: all layers emit dinv-scaled fp16 hs; aggregates accumulate fp32
    k_gemm<FIN, HID, false, false, OM_H16S><<<gemmBlocks, 128>>>(x, nullptr, W1, N);
    k_agg16<HID, false><<<agg64Blocks, T>>>(N, nullptr, nullptr);

    k_gemm<HID, HID, true, true, OM_H16S><<<gemmBlocks, 128>>>(nullptr, b1, W2, N);
    k_agg16<HID, false><<<agg64Blocks, T>>>(N, nullptr, nullptr);

    k_gemm<HID, OUTD, true, true, OM_H16S><<<gemmBlocks, 64>>>(nullptr, b2, W3, N);
    k_agg16<OUTD, true><<<agg32Blocks, T>>>(N, b3, zout);

    // fused decoder precompute: [u|v] = z @ [lpW1_top | lpW1_bot] (fp16 out)
    k_gemm<OUTD, 128, false, false, OM_SPLIT16><<<gemmBlocks, 256>>>(zout, nullptr, lpW1, N);

    // decoder-lite: 4 edges/warp, fp16 gathers
    int warpsD = (EL + 3) / 4;
    int decBlocks = (warpsD * 32 + T - 1) / T;
    k_decode_lite<<<decBlocks, T>>>(eli, lpb1, lpW2, lpb2, out, EL, N);
}